// round 8
// baseline (speedup 1.0000x reference)
#include <cuda_runtime.h>

#define G_TOTAL 32768
#define H1      150
#define PP      8

using u64 = unsigned long long;

// ---- packed f32x2 helpers (Blackwell sm_103a) ------------------------------
__device__ __forceinline__ u64 pk2(float a, float b) {
    u64 r;
    asm("mov.b64 %0,{%1,%2};" : "=l"(r)
        : "r"(__float_as_uint(a)), "r"(__float_as_uint(b)));
    return r;
}
__device__ __forceinline__ float2 upk2(u64 v) {
    unsigned lo, hi;
    asm("mov.b64 {%0,%1},%2;" : "=r"(lo), "=r"(hi) : "l"(v));
    return make_float2(__uint_as_float(lo), __uint_as_float(hi));
}
__device__ __forceinline__ u64 fma2(u64 a, u64 b, u64 c) {
    u64 d;
    asm("fma.rn.f32x2 %0,%1,%2,%3;" : "=l"(d) : "l"(a), "l"(b), "l"(c));
    return d;
}
__device__ __forceinline__ u64 add2(u64 a, u64 b) {
    u64 d;
    asm("add.rn.f32x2 %0,%1,%2;" : "=l"(d) : "l"(a), "l"(b));
    return d;
}
__device__ __forceinline__ u64 relu2(u64 v) {
    float2 t = upk2(v);
    return pk2(fmaxf(t.x, 0.0f), fmaxf(t.y, 0.0f));
}

// ---- shared-memory layout (float offsets) ----------------------------------
// H padded 150 -> 152 (zero weights; exact: relu(0)=0 and W2 pad rows are 0)
// W1n : [18][152]  natural k-major W1 rows -> LDS.128 j-quads
// W2p : [76][8]    u64 pairs {W2[2jp][p], W2[2jp+1][p]} (pad jp=75 zero)
// b1s : [152]
// W3t : [150][40]  transposed W3 rows (lane-distinct tail)
// EX  : [4][32][8] u64 ACC exchange between j-half teams
#define SM_W1N 0
#define SM_W2P 2736
#define SM_B1  3952
#define SM_W3T 4104
#define SM_B3  10104
#define SM_W4  10256
#define SM_B2  10408
#define SM_EX  10416
#define SM_FLOATS (10416 + 4 * 32 * 8 * 2)
#define SM_BYTES  (SM_FLOATS * 4)

// ---- per-group tail: warp stats over 32 lanes + group MLP (verified) -------
__device__ __noinline__ float group_tail(const float* a,
                                         const float* __restrict__ W3t,
                                         const float* __restrict__ b3s,
                                         const float* __restrict__ W4s,
                                         float b4v, int lane)
{
    u64 ag[20];   // packed agg pairs: ag[stat*4 + p/2] = {agg_p, agg_p+1}

    #pragma unroll
    for (int ph = 0; ph < 4; ++ph) {
        float va = a[2 * ph], vb = a[2 * ph + 1];

        // mean
        float sa = va, sb = vb;
        #pragma unroll
        for (int o = 16; o; o >>= 1) {
            sa += __shfl_xor_sync(0xffffffffu, sa, o);
            sb += __shfl_xor_sync(0xffffffffu, sb, o);
        }
        float meana = sa * (1.0f / 32.0f), meanb = sb * (1.0f / 32.0f);

        // unbiased variance (two-pass)
        float da = va - meana, db = vb - meanb;
        float qa = da * da, qb = db * db;
        #pragma unroll
        for (int o = 16; o; o >>= 1) {
            qa += __shfl_xor_sync(0xffffffffu, qa, o);
            qb += __shfl_xor_sync(0xffffffffu, qb, o);
        }
        float vara = qa * (1.0f / 31.0f), varb = qb * (1.0f / 31.0f);

        // min / max
        float mna = va, mxa = va, mnb = vb, mxb = vb;
        #pragma unroll
        for (int o = 16; o; o >>= 1) {
            mna = fminf(mna, __shfl_xor_sync(0xffffffffu, mna, o));
            mxa = fmaxf(mxa, __shfl_xor_sync(0xffffffffu, mxa, o));
            mnb = fminf(mnb, __shfl_xor_sync(0xffffffffu, mnb, o));
            mxb = fmaxf(mxb, __shfl_xor_sync(0xffffffffu, mxb, o));
        }

        // lower median via warp bitonic sort (two sorts interleaved)
        float ta = va, tb = vb;
        #pragma unroll
        for (int k = 2; k <= 32; k <<= 1) {
            #pragma unroll
            for (int j = k >> 1; j > 0; j >>= 1) {
                float oa = __shfl_xor_sync(0xffffffffu, ta, j);
                float ob = __shfl_xor_sync(0xffffffffu, tb, j);
                bool keep_lo = (((lane & j) == 0) == ((lane & k) == 0));
                float la = fminf(ta, oa), ha = fmaxf(ta, oa);
                float lb = fminf(tb, ob), hb = fmaxf(tb, ob);
                ta = keep_lo ? la : ha;
                tb = keep_lo ? lb : hb;
            }
        }
        float meda = __shfl_sync(0xffffffffu, ta, 15);
        float medb = __shfl_sync(0xffffffffu, tb, 15);

        ag[0 * 4 + ph] = pk2(meana, meanb);
        ag[1 * 4 + ph] = pk2(vara, varb);
        ag[2 * 4 + ph] = pk2(mna, mnb);
        ag[3 * 4 + ph] = pk2(meda, medb);
        ag[4 * 4 + ph] = pk2(mxa, mxb);
    }

    // group MLP: 40 -> 150 (relu) -> 1, hidden units strided over lanes
    float zp = 0.0f;
    #pragma unroll 1
    for (int j = lane; j < H1; j += 32) {
        const ulonglong2* wr = (const ulonglong2*)(W3t + j * 40);
        u64 t2a = 0ull, t2b = 0ull;
        #pragma unroll
        for (int q = 0; q < 10; ++q) {
            ulonglong2 w = wr[q];
            t2a = fma2(ag[2 * q],     w.x, t2a);
            t2b = fma2(ag[2 * q + 1], w.y, t2b);
        }
        float2 sa = upk2(t2a), sb = upk2(t2b);
        float t = (sa.x + sa.y) + (sb.x + sb.y) + b3s[j];
        t = fmaxf(t, 0.0f);
        zp = fmaf(t, W4s[j], zp);
    }
    #pragma unroll
    for (int o = 16; o; o >>= 1) zp += __shfl_xor_sync(0xffffffffu, zp, o);

    return 1.0f / (1.0f + __expf(-(zp + b4v)));
}

__global__ void __launch_bounds__(128, 3)
minn_fused_jsplit_kernel(const float* __restrict__ x,
                         const int*   __restrict__ kmer,
                         const int*   __restrict__ indices,
                         const float* __restrict__ emb,
                         const float* __restrict__ W1, const float* __restrict__ b1,
                         const float* __restrict__ W2, const float* __restrict__ b2,
                         const float* __restrict__ W3, const float* __restrict__ b3,
                         const float* __restrict__ W4, const float* __restrict__ b4,
                         float* __restrict__ out)
{
    extern __shared__ float sm[];
    float* W1n  = sm + SM_W1N;
    u64*   W2pu = (u64*)(sm + SM_W2P);
    float* b1s  = sm + SM_B1;
    float* W3t  = sm + SM_W3T;
    float* b3s  = sm + SM_B3;
    float* W4s  = sm + SM_W4;
    float* b2s  = sm + SM_B2;
    u64*   ex   = (u64*)(sm + SM_EX);

    const int tid = threadIdx.x;

    // ---- stage weights (natural layouts; no duplication anywhere) ----
    for (int i = tid; i < 18 * 152; i += 128) {
        int k = i / 152, j = i - k * 152;
        W1n[i] = (j < H1) ? W1[k * H1 + j] : 0.0f;
    }
    for (int i = tid; i < 76 * PP; i += 128) {
        int jp = i >> 3, p = i & 7;
        int j0 = 2 * jp, j1 = 2 * jp + 1;
        float w0 = (j0 < H1) ? W2[j0 * PP + p] : 0.0f;
        float w1 = (j1 < H1) ? W2[j1 * PP + p] : 0.0f;
        W2pu[i] = pk2(w0, w1);
    }
    for (int i = tid; i < 152; i += 128)
        b1s[i] = (i < H1) ? b1[i] : 0.0f;
    for (int i = tid; i < 40 * H1; i += 128) {
        int j = i / 40, k = i - j * 40;
        W3t[i] = W3[k * H1 + j];
    }
    for (int i = tid; i < H1; i += 128) {
        b3s[i] = b3[i];
        W4s[i] = W4[i];
    }
    if (tid < PP) b2s[tid] = b2[tid];
    const float b4v = __ldg(b4);
    __syncthreads();

    const int warp = tid >> 5;          // 0..3
    const int lane = tid & 31;
    const int team = warp >> 1;         // 0: j in [0,76), 1: j in [76,152)
    const int slot = warp & 1;          // which 4-group set of the block
    const int g0 = (blockIdx.x * 2 + slot) * 4;   // 4 groups per slot

    // ---- gather the 4 reads this lane owns, packed read-pair-wise ----
    const int r0 = indices[(g0 + 0) * 32 + lane];
    const int r1 = indices[(g0 + 1) * 32 + lane];
    const int r2 = indices[(g0 + 2) * 32 + lane];
    const int r3 = indices[(g0 + 3) * 32 + lane];

    u64 rp0[18], rp1[18];   // rp0[k]={r0[k],r1[k]}, rp1[k]={r2[k],r3[k]}
    {
        const float4* p0 = (const float4*)(x + (size_t)r0 * 16);
        const float4* p1 = (const float4*)(x + (size_t)r1 * 16);
        const float4* p2 = (const float4*)(x + (size_t)r2 * 16);
        const float4* p3 = (const float4*)(x + (size_t)r3 * 16);
        #pragma unroll
        for (int q = 0; q < 4; ++q) {
            float4 v0 = p0[q], v1 = p1[q], v2 = p2[q], v3 = p3[q];
            rp0[4 * q + 0] = pk2(v0.x, v1.x);  rp1[4 * q + 0] = pk2(v2.x, v3.x);
            rp0[4 * q + 1] = pk2(v0.y, v1.y);  rp1[4 * q + 1] = pk2(v2.y, v3.y);
            rp0[4 * q + 2] = pk2(v0.z, v1.z);  rp1[4 * q + 2] = pk2(v2.z, v3.z);
            rp0[4 * q + 3] = pk2(v0.w, v1.w);  rp1[4 * q + 3] = pk2(v2.w, v3.w);
        }
        float2 e0 = ((const float2*)emb)[kmer[r0]];
        float2 e1 = ((const float2*)emb)[kmer[r1]];
        float2 e2 = ((const float2*)emb)[kmer[r2]];
        float2 e3 = ((const float2*)emb)[kmer[r3]];
        rp0[16] = pk2(e0.x, e1.x);  rp1[16] = pk2(e2.x, e3.x);
        rp0[17] = pk2(e0.y, e1.y);  rp1[17] = pk2(e2.y, e3.y);
    }

    // ---- per-read MLP via diagonal f32x2; this warp covers HALF the j's ----
    u64 ACC0[PP], ACC1[PP];
    #pragma unroll
    for (int p = 0; p < PP; ++p) { ACC0[p] = 0ull; ACC1[p] = 0ull; }

    const int jp2_beg = team * 19;
    const int jp2_end = jp2_beg + 19;

    #pragma unroll 1
    for (int jp2 = jp2_beg; jp2 < jp2_end; ++jp2) {
        float4 bq = *(const float4*)(b1s + 4 * jp2);      // LDS.128
        u64 BpA = pk2(bq.x, bq.y), BsA = pk2(bq.y, bq.x);
        u64 BpB = pk2(bq.z, bq.w), BsB = pk2(bq.w, bq.z);
        u64 A00 = BpA, A01 = BsA, A10 = BpA, A11 = BsA;
        u64 C00 = BpB, C01 = BsB, C10 = BpB, C11 = BsB;

        const float* w1c = W1n + 4 * jp2;
        #pragma unroll
        for (int k = 0; k < 18; ++k) {
            float4 wq = *(const float4*)(w1c + k * 152);  // LDS.128: 4 j's
            u64 wpA = pk2(wq.x, wq.y), wsA = pk2(wq.y, wq.x);
            u64 wpB = pk2(wq.z, wq.w), wsB = pk2(wq.w, wq.z);
            A00 = fma2(rp0[k], wpA, A00);
            A01 = fma2(rp0[k], wsA, A01);
            A10 = fma2(rp1[k], wpA, A10);
            A11 = fma2(rp1[k], wsA, A11);
            C00 = fma2(rp0[k], wpB, C00);
            C01 = fma2(rp0[k], wsB, C01);
            C10 = fma2(rp1[k], wpB, C10);
            C11 = fma2(rp1[k], wsB, C11);
        }
        A00 = relu2(A00);  A01 = relu2(A01);
        A10 = relu2(A10);  A11 = relu2(A11);
        C00 = relu2(C00);  C01 = relu2(C01);
        C10 = relu2(C10);  C11 = relu2(C11);

        const ulonglong2* w2a = (const ulonglong2*)(W2pu + (2 * jp2) * PP);
        const ulonglong2* w2b = (const ulonglong2*)(W2pu + (2 * jp2 + 1) * PP);
        #pragma unroll
        for (int q = 0; q < 4; ++q) {
            ulonglong2 wa = w2a[q];
            ulonglong2 wb = w2b[q];
            float2 wa0 = upk2(wa.x), wa1 = upk2(wa.y);
            float2 wb0 = upk2(wb.x), wb1 = upk2(wb.y);
            u64 wap0 = pk2(wa0.x, wa0.y), was0 = pk2(wa0.y, wa0.x);
            u64 wap1 = pk2(wa1.x, wa1.y), was1 = pk2(wa1.y, wa1.x);
            u64 wbp0 = pk2(wb0.x, wb0.y), wbs0 = pk2(wb0.y, wb0.x);
            u64 wbp1 = pk2(wb1.x, wb1.y), wbs1 = pk2(wb1.y, wb1.x);

            ACC0[2 * q]     = fma2(A00, wap0, ACC0[2 * q]);
            ACC0[2 * q]     = fma2(A01, was0, ACC0[2 * q]);
            ACC0[2 * q]     = fma2(C00, wbp0, ACC0[2 * q]);
            ACC0[2 * q]     = fma2(C01, wbs0, ACC0[2 * q]);
            ACC0[2 * q + 1] = fma2(A00, wap1, ACC0[2 * q + 1]);
            ACC0[2 * q + 1] = fma2(A01, was1, ACC0[2 * q + 1]);
            ACC0[2 * q + 1] = fma2(C00, wbp1, ACC0[2 * q + 1]);
            ACC0[2 * q + 1] = fma2(C01, wbs1, ACC0[2 * q + 1]);

            ACC1[2 * q]     = fma2(A10, wap0, ACC1[2 * q]);
            ACC1[2 * q]     = fma2(A11, was0, ACC1[2 * q]);
            ACC1[2 * q]     = fma2(C10, wbp0, ACC1[2 * q]);
            ACC1[2 * q]     = fma2(C11, wbs0, ACC1[2 * q]);
            ACC1[2 * q + 1] = fma2(A10, wap1, ACC1[2 * q + 1]);
            ACC1[2 * q + 1] = fma2(A11, was1, ACC1[2 * q + 1]);
            ACC1[2 * q + 1] = fma2(C10, wbp1, ACC1[2 * q + 1]);
            ACC1[2 * q + 1] = fma2(C11, wbs1, ACC1[2 * q + 1]);
        }
    }

    // ---- exchange partial ACCs between j-half teams ----
    // team 0 keeps groups {g0, g0+1} (ACC0); team 1 keeps {g0+2, g0+3} (ACC1).
    {
        u64* mine = ex + (warp * 32 + lane) * PP;
        if (team == 0) {
            #pragma unroll
            for (int p = 0; p < PP; ++p) mine[p] = ACC1[p];
        } else {
            #pragma unroll
            for (int p = 0; p < PP; ++p) mine[p] = ACC0[p];
        }
    }
    __syncthreads();
    {
        const int peer = (team == 0) ? (warp + 2) : (warp - 2);
        const u64* theirs = ex + (peer * 32 + lane) * PP;
        if (team == 0) {
            #pragma unroll
            for (int p = 0; p < PP; ++p) ACC0[p] = add2(ACC0[p], theirs[p]);
        } else {
            #pragma unroll
            for (int p = 0; p < PP; ++p) ACC1[p] = add2(ACC1[p], theirs[p]);
        }
    }

    // add b2, final relu, unpack this team's two groups
    float sA[PP], sB[PP];
    #pragma unroll
    for (int p = 0; p < PP; ++p) {
        float bp = b2s[p];
        float2 t = (team == 0) ? upk2(ACC0[p]) : upk2(ACC1[p]);
        sA[p] = fmaxf(t.x + bp, 0.0f);
        sB[p] = fmaxf(t.y + bp, 0.0f);
    }

    // ---- per-group aggregation + group MLP (2 groups per warp) ----
    const int gb = g0 + team * 2;
    float oA = group_tail(sA, W3t, b3s, W4s, b4v, lane);
    if (lane == 0) out[gb + 0] = oA;
    float oB = group_tail(sB, W3t, b3s, W4s, b4v, lane);
    if (lane == 0) out[gb + 1] = oB;
}

extern "C" void kernel_launch(void* const* d_in, const int* in_sizes, int n_in,
                              void* d_out, int out_size)
{
    const float* x       = (const float*)d_in[0];
    const int*   kmer    = (const int*)  d_in[1];
    const int*   indices = (const int*)  d_in[2];
    const float* emb     = (const float*)d_in[3];
    const float* W1      = (const float*)d_in[4];
    const float* b1      = (const float*)d_in[5];
    const float* W2      = (const float*)d_in[6];
    const float* b2      = (const float*)d_in[7];
    const float* W3      = (const float*)d_in[8];
    const float* b3      = (const float*)d_in[9];
    const float* W4      = (const float*)d_in[10];
    const float* b4      = (const float*)d_in[11];
    float* out = (float*)d_out;

    cudaFuncSetAttribute(minn_fused_jsplit_kernel,
                         cudaFuncAttributeMaxDynamicSharedMemorySize, SM_BYTES);

    // 4 warps/block (2 teams x 2 slots), 8 groups per block
    const int blocks = G_TOTAL / 8;   // 4096
    minn_fused_jsplit_kernel<<<blocks, 128, SM_BYTES>>>(
        x, kmer, indices, emb, W1, b1, W2, b2, W3, b3, W4, b4, out);
}

// round 10
// speedup vs baseline: 1.1484x; 1.1484x over previous
#include <cuda_runtime.h>

#define G_TOTAL 32768
#define H1      150
#define PP      8

using u64 = unsigned long long;

// ---- packed f32x2 helpers (Blackwell sm_103a) ------------------------------
__device__ __forceinline__ u64 pk2(float a, float b) {
    u64 r;
    asm("mov.b64 %0,{%1,%2};" : "=l"(r)
        : "r"(__float_as_uint(a)), "r"(__float_as_uint(b)));
    return r;
}
__device__ __forceinline__ float2 upk2(u64 v) {
    unsigned lo, hi;
    asm("mov.b64 {%0,%1},%2;" : "=r"(lo), "=r"(hi) : "l"(v));
    return make_float2(__uint_as_float(lo), __uint_as_float(hi));
}
__device__ __forceinline__ u64 fma2(u64 a, u64 b, u64 c) {
    u64 d;
    asm("fma.rn.f32x2 %0,%1,%2,%3;" : "=l"(d) : "l"(a), "l"(b), "l"(c));
    return d;
}
__device__ __forceinline__ u64 relu2(u64 v) {
    float2 t = upk2(v);
    return pk2(fmaxf(t.x, 0.0f), fmaxf(t.y, 0.0f));
}

// ---- shared-memory layout (float offsets) ----------------------------------
// H padded 150 -> 152 (zero weights; exact: relu(0)=0 and W2 pad rows are 0)
// W1n : [18][152]  natural k-major W1 rows -> LDS.128 j-quads
// W2p : [76][8]    u64 pairs {W2[2jp][p], W2[2jp+1][p]} (pad jp=75 zero)
// b1s : [152]
// W3t : [150][40]  transposed W3 rows (lane-distinct tail)
#define SM_W1N 0
#define SM_W2P 2736
#define SM_B1  3952
#define SM_W3T 4104
#define SM_B3  10104
#define SM_W4  10256
#define SM_B2  10408
#define SM_FLOATS 10416
#define SM_BYTES  (SM_FLOATS * 4)

// ---- per-group tail: warp stats over 32 lanes + group MLP (verified) -------
__device__ __noinline__ float group_tail(const float* a,
                                         const float* __restrict__ W3t,
                                         const float* __restrict__ b3s,
                                         const float* __restrict__ W4s,
                                         float b4v, int lane)
{
    u64 ag[20];   // packed agg pairs: ag[stat*4 + p/2] = {agg_p, agg_p+1}

    #pragma unroll
    for (int ph = 0; ph < 4; ++ph) {
        float va = a[2 * ph], vb = a[2 * ph + 1];

        // mean
        float sa = va, sb = vb;
        #pragma unroll
        for (int o = 16; o; o >>= 1) {
            sa += __shfl_xor_sync(0xffffffffu, sa, o);
            sb += __shfl_xor_sync(0xffffffffu, sb, o);
        }
        float meana = sa * (1.0f / 32.0f), meanb = sb * (1.0f / 32.0f);

        // unbiased variance (two-pass)
        float da = va - meana, db = vb - meanb;
        float qa = da * da, qb = db * db;
        #pragma unroll
        for (int o = 16; o; o >>= 1) {
            qa += __shfl_xor_sync(0xffffffffu, qa, o);
            qb += __shfl_xor_sync(0xffffffffu, qb, o);
        }
        float vara = qa * (1.0f / 31.0f), varb = qb * (1.0f / 31.0f);

        // min / max
        float mna = va, mxa = va, mnb = vb, mxb = vb;
        #pragma unroll
        for (int o = 16; o; o >>= 1) {
            mna = fminf(mna, __shfl_xor_sync(0xffffffffu, mna, o));
            mxa = fmaxf(mxa, __shfl_xor_sync(0xffffffffu, mxa, o));
            mnb = fminf(mnb, __shfl_xor_sync(0xffffffffu, mnb, o));
            mxb = fmaxf(mxb, __shfl_xor_sync(0xffffffffu, mxb, o));
        }

        // lower median via warp bitonic sort (two sorts interleaved)
        float ta = va, tb = vb;
        #pragma unroll
        for (int k = 2; k <= 32; k <<= 1) {
            #pragma unroll
            for (int j = k >> 1; j > 0; j >>= 1) {
                float oa = __shfl_xor_sync(0xffffffffu, ta, j);
                float ob = __shfl_xor_sync(0xffffffffu, tb, j);
                bool keep_lo = (((lane & j) == 0) == ((lane & k) == 0));
                float la = fminf(ta, oa), ha = fmaxf(ta, oa);
                float lb = fminf(tb, ob), hb = fmaxf(tb, ob);
                ta = keep_lo ? la : ha;
                tb = keep_lo ? lb : hb;
            }
        }
        float meda = __shfl_sync(0xffffffffu, ta, 15);
        float medb = __shfl_sync(0xffffffffu, tb, 15);

        ag[0 * 4 + ph] = pk2(meana, meanb);
        ag[1 * 4 + ph] = pk2(vara, varb);
        ag[2 * 4 + ph] = pk2(mna, mnb);
        ag[3 * 4 + ph] = pk2(meda, medb);
        ag[4 * 4 + ph] = pk2(mxa, mxb);
    }

    // group MLP: 40 -> 150 (relu) -> 1, hidden units strided over lanes
    float zp = 0.0f;
    #pragma unroll 1
    for (int j = lane; j < H1; j += 32) {
        const ulonglong2* wr = (const ulonglong2*)(W3t + j * 40);
        u64 t2a = 0ull, t2b = 0ull;
        #pragma unroll
        for (int q = 0; q < 10; ++q) {
            ulonglong2 w = wr[q];
            t2a = fma2(ag[2 * q],     w.x, t2a);
            t2b = fma2(ag[2 * q + 1], w.y, t2b);
        }
        float2 sa = upk2(t2a), sb = upk2(t2b);
        float t = (sa.x + sa.y) + (sb.x + sb.y) + b3s[j];
        t = fmaxf(t, 0.0f);
        zp = fmaf(t, W4s[j], zp);
    }
    #pragma unroll
    for (int o = 16; o; o >>= 1) zp += __shfl_xor_sync(0xffffffffu, zp, o);

    return 1.0f / (1.0f + __expf(-(zp + b4v)));
}

__global__ void __launch_bounds__(128, 3)
minn_fused_diag3_kernel(const float* __restrict__ x,
                        const int*   __restrict__ kmer,
                        const int*   __restrict__ indices,
                        const float* __restrict__ emb,
                        const float* __restrict__ W1, const float* __restrict__ b1,
                        const float* __restrict__ W2, const float* __restrict__ b2,
                        const float* __restrict__ W3, const float* __restrict__ b3,
                        const float* __restrict__ W4, const float* __restrict__ b4,
                        float* __restrict__ out)
{
    extern __shared__ float sm[];
    float* W1n  = sm + SM_W1N;
    u64*   W2pu = (u64*)(sm + SM_W2P);
    float* b1s  = sm + SM_B1;
    float* W3t  = sm + SM_W3T;
    float* b3s  = sm + SM_B3;
    float* W4s  = sm + SM_W4;
    float* b2s  = sm + SM_B2;

    const int tid = threadIdx.x;

    // ---- stage weights (natural layouts; no duplication anywhere) ----
    for (int i = tid; i < 18 * 152; i += 128) {
        int k = i / 152, j = i - k * 152;
        W1n[i] = (j < H1) ? W1[k * H1 + j] : 0.0f;
    }
    for (int i = tid; i < 76 * PP; i += 128) {
        int jp = i >> 3, p = i & 7;
        int j0 = 2 * jp, j1 = 2 * jp + 1;
        float w0 = (j0 < H1) ? W2[j0 * PP + p] : 0.0f;
        float w1 = (j1 < H1) ? W2[j1 * PP + p] : 0.0f;
        W2pu[i] = pk2(w0, w1);
    }
    for (int i = tid; i < 152; i += 128)
        b1s[i] = (i < H1) ? b1[i] : 0.0f;
    for (int i = tid; i < 40 * H1; i += 128) {
        int j = i / 40, k = i - j * 40;
        W3t[i] = W3[k * H1 + j];
    }
    for (int i = tid; i < H1; i += 128) {
        b3s[i] = b3[i];
        W4s[i] = W4[i];
    }
    if (tid < PP) b2s[tid] = b2[tid];
    const float b4v = __ldg(b4);
    __syncthreads();

    const int warp = tid >> 5;
    const int lane = tid & 31;
    const int g0 = (blockIdx.x * 4 + warp) * 4;   // 4 groups per warp

    // ---- gather the 4 reads this lane owns, packed read-pair-wise ----
    const int r0 = indices[(g0 + 0) * 32 + lane];
    const int r1 = indices[(g0 + 1) * 32 + lane];
    const int r2 = indices[(g0 + 2) * 32 + lane];
    const int r3 = indices[(g0 + 3) * 32 + lane];

    u64 rp0[18], rp1[18];   // rp0[k]={r0[k],r1[k]}, rp1[k]={r2[k],r3[k]}
    {
        const float4* p0 = (const float4*)(x + (size_t)r0 * 16);
        const float4* p1 = (const float4*)(x + (size_t)r1 * 16);
        const float4* p2 = (const float4*)(x + (size_t)r2 * 16);
        const float4* p3 = (const float4*)(x + (size_t)r3 * 16);
        #pragma unroll
        for (int q = 0; q < 4; ++q) {
            float4 v0 = p0[q], v1 = p1[q], v2 = p2[q], v3 = p3[q];
            rp0[4 * q + 0] = pk2(v0.x, v1.x);  rp1[4 * q + 0] = pk2(v2.x, v3.x);
            rp0[4 * q + 1] = pk2(v0.y, v1.y);  rp1[4 * q + 1] = pk2(v2.y, v3.y);
            rp0[4 * q + 2] = pk2(v0.z, v1.z);  rp1[4 * q + 2] = pk2(v2.z, v3.z);
            rp0[4 * q + 3] = pk2(v0.w, v1.w);  rp1[4 * q + 3] = pk2(v2.w, v3.w);
        }
        float2 e0 = ((const float2*)emb)[kmer[r0]];
        float2 e1 = ((const float2*)emb)[kmer[r1]];
        float2 e2 = ((const float2*)emb)[kmer[r2]];
        float2 e3 = ((const float2*)emb)[kmer[r3]];
        rp0[16] = pk2(e0.x, e1.x);  rp1[16] = pk2(e2.x, e3.x);
        rp0[17] = pk2(e0.y, e1.y);  rp1[17] = pk2(e2.y, e3.y);
    }

    // ---- per-read MLP via diagonal f32x2, two j-pairs per iteration ----
    u64 ACC0[PP], ACC1[PP];
    #pragma unroll
    for (int p = 0; p < PP; ++p) { ACC0[p] = 0ull; ACC1[p] = 0ull; }

    #pragma unroll 1
    for (int jp2 = 0; jp2 < 38; ++jp2) {
        // --- hoisted loads: W2 (4+4 x LDS.128) and b (LDS.128) issue FIRST so
        //     their latency hides under the k-loop below ---
        ulonglong2 w2a0, w2a1, w2a2, w2a3, w2b0, w2b1, w2b2, w2b3;
        {
            const ulonglong2* w2a = (const ulonglong2*)(W2pu + (2 * jp2) * PP);
            const ulonglong2* w2b = (const ulonglong2*)(W2pu + (2 * jp2 + 1) * PP);
            w2a0 = w2a[0]; w2a1 = w2a[1]; w2a2 = w2a[2]; w2a3 = w2a[3];
            w2b0 = w2b[0]; w2b1 = w2b[1]; w2b2 = w2b[2]; w2b3 = w2b[3];
        }
        float4 bq = *(const float4*)(b1s + 4 * jp2);

        const float* w1c = W1n + 4 * jp2;
        // 2-deep rolling prefetch of W1 quads
        float4 wf0 = *(const float4*)(w1c + 0 * 152);
        float4 wf1 = *(const float4*)(w1c + 1 * 152);

        u64 BpA = pk2(bq.x, bq.y), BsA = pk2(bq.y, bq.x);
        u64 BpB = pk2(bq.z, bq.w), BsB = pk2(bq.w, bq.z);
        u64 A00 = BpA, A01 = BsA, A10 = BpA, A11 = BsA;
        u64 C00 = BpB, C01 = BsB, C10 = BpB, C11 = BsB;

        #pragma unroll
        for (int k = 0; k < 18; ++k) {
            float4 wq = (k & 1) ? wf1 : wf0;
            if (k + 2 < 18) {
                float4 nxt = *(const float4*)(w1c + (k + 2) * 152);
                if (k & 1) wf1 = nxt; else wf0 = nxt;
            }
            u64 wpA = pk2(wq.x, wq.y), wsA = pk2(wq.y, wq.x);
            u64 wpB = pk2(wq.z, wq.w), wsB = pk2(wq.w, wq.z);
            A00 = fma2(rp0[k], wpA, A00);
            A01 = fma2(rp0[k], wsA, A01);
            A10 = fma2(rp1[k], wpA, A10);
            A11 = fma2(rp1[k], wsA, A11);
            C00 = fma2(rp0[k], wpB, C00);
            C01 = fma2(rp0[k], wsB, C01);
            C10 = fma2(rp1[k], wpB, C10);
            C11 = fma2(rp1[k], wsB, C11);
        }
        A00 = relu2(A00);  A01 = relu2(A01);
        A10 = relu2(A10);  A11 = relu2(A11);
        C00 = relu2(C00);  C01 = relu2(C01);
        C10 = relu2(C10);  C11 = relu2(C11);

        #pragma unroll
        for (int q = 0; q < 4; ++q) {
            ulonglong2 wa = (q == 0) ? w2a0 : (q == 1) ? w2a1 : (q == 2) ? w2a2 : w2a3;
            ulonglong2 wb = (q == 0) ? w2b0 : (q == 1) ? w2b1 : (q == 2) ? w2b2 : w2b3;
            float2 wa0 = upk2(wa.x), wa1 = upk2(wa.y);
            float2 wb0 = upk2(wb.x), wb1 = upk2(wb.y);
            u64 wap0 = pk2(wa0.x, wa0.y), was0 = pk2(wa0.y, wa0.x);
            u64 wap1 = pk2(wa1.x, wa1.y), was1 = pk2(wa1.y, wa1.x);
            u64 wbp0 = pk2(wb0.x, wb0.y), wbs0 = pk2(wb0.y, wb0.x);
            u64 wbp1 = pk2(wb1.x, wb1.y), wbs1 = pk2(wb1.y, wb1.x);

            ACC0[2 * q]     = fma2(A00, wap0, ACC0[2 * q]);
            ACC0[2 * q]     = fma2(A01, was0, ACC0[2 * q]);
            ACC0[2 * q]     = fma2(C00, wbp0, ACC0[2 * q]);
            ACC0[2 * q]     = fma2(C01, wbs0, ACC0[2 * q]);
            ACC0[2 * q + 1] = fma2(A00, wap1, ACC0[2 * q + 1]);
            ACC0[2 * q + 1] = fma2(A01, was1, ACC0[2 * q + 1]);
            ACC0[2 * q + 1] = fma2(C00, wbp1, ACC0[2 * q + 1]);
            ACC0[2 * q + 1] = fma2(C01, wbs1, ACC0[2 * q + 1]);

            ACC1[2 * q]     = fma2(A10, wap0, ACC1[2 * q]);
            ACC1[2 * q]     = fma2(A11, was0, ACC1[2 * q]);
            ACC1[2 * q]     = fma2(C10, wbp0, ACC1[2 * q]);
            ACC1[2 * q]     = fma2(C11, wbs0, ACC1[2 * q]);
            ACC1[2 * q + 1] = fma2(A10, wap1, ACC1[2 * q + 1]);
            ACC1[2 * q + 1] = fma2(A11, was1, ACC1[2 * q + 1]);
            ACC1[2 * q + 1] = fma2(C10, wbp1, ACC1[2 * q + 1]);
            ACC1[2 * q + 1] = fma2(C11, wbs1, ACC1[2 * q + 1]);
        }
    }

    // add b2, final relu, unpack per-group activations
    float s0[PP], s1[PP], s2[PP], s3[PP];
    #pragma unroll
    for (int p = 0; p < PP; ++p) {
        float bp = b2s[p];
        float2 t = upk2(ACC0[p]);
        s0[p] = fmaxf(t.x + bp, 0.0f);
        s1[p] = fmaxf(t.y + bp, 0.0f);
        float2 u = upk2(ACC1[p]);
        s2[p] = fmaxf(u.x + bp, 0.0f);
        s3[p] = fmaxf(u.y + bp, 0.0f);
    }

    // ---- per-group aggregation + group MLP ----
    float o0 = group_tail(s0, W3t, b3s, W4s, b4v, lane);
    if (lane == 0) out[g0 + 0] = o0;
    float o1 = group_tail(s1, W3t, b3s, W4s, b4v, lane);
    if (lane == 0) out[g0 + 1] = o1;
    float o2 = group_tail(s2, W3t, b3s, W4s, b4v, lane);
    if (lane == 0) out[g0 + 2] = o2;
    float o3 = group_tail(s3, W3t, b3s, W4s, b4v, lane);
    if (lane == 0) out[g0 + 3] = o3;
}

extern "C" void kernel_launch(void* const* d_in, const int* in_sizes, int n_in,
                              void* d_out, int out_size)
{
    const float* x       = (const float*)d_in[0];
    const int*   kmer    = (const int*)  d_in[1];
    const int*   indices = (const int*)  d_in[2];
    const float* emb     = (const float*)d_in[3];
    const float* W1      = (const float*)d_in[4];
    const float* b1      = (const float*)d_in[5];
    const float* W2      = (const float*)d_in[6];
    const float* b2      = (const float*)d_in[7];
    const float* W3      = (const float*)d_in[8];
    const float* b3      = (const float*)d_in[9];
    const float* W4      = (const float*)d_in[10];
    const float* b4      = (const float*)d_in[11];
    float* out = (float*)d_out;

    cudaFuncSetAttribute(minn_fused_diag3_kernel,
                         cudaFuncAttributeMaxDynamicSharedMemorySize, SM_BYTES);

    // 4 warps/block * 4 groups/warp = 16 groups per block
    const int blocks = G_TOTAL / 16;   // 2048
    minn_fused_diag3_kernel<<<blocks, 128, SM_BYTES>>>(
        x, kmer, indices, emb, W1, b1, W2, b2, W3, b3, W4, b4, out);
}

// round 11
// speedup vs baseline: 1.1509x; 1.0022x over previous
#include <cuda_runtime.h>

#define G_TOTAL 32768
#define H1      150
#define PP      8

using u64 = unsigned long long;

// ---- packed f32x2 helpers (Blackwell sm_103a) ------------------------------
__device__ __forceinline__ u64 pk2(float a, float b) {
    u64 r;
    asm("mov.b64 %0,{%1,%2};" : "=l"(r)
        : "r"(__float_as_uint(a)), "r"(__float_as_uint(b)));
    return r;
}
__device__ __forceinline__ float2 upk2(u64 v) {
    unsigned lo, hi;
    asm("mov.b64 {%0,%1},%2;" : "=r"(lo), "=r"(hi) : "l"(v));
    return make_float2(__uint_as_float(lo), __uint_as_float(hi));
}
__device__ __forceinline__ u64 fma2(u64 a, u64 b, u64 c) {
    u64 d;
    asm("fma.rn.f32x2 %0,%1,%2,%3;" : "=l"(d) : "l"(a), "l"(b), "l"(c));
    return d;
}
__device__ __forceinline__ u64 relu2(u64 v) {
    float2 t = upk2(v);
    return pk2(fmaxf(t.x, 0.0f), fmaxf(t.y, 0.0f));
}

// ---- shared-memory layout (float offsets) ----------------------------------
// H padded 150 -> 152 (zero weights; exact: relu(0)=0 and W2 pad rows are 0)
// W1n : [18][152]  natural k-major W1 rows -> LDS.128 j-quads
// W2p : [76][8]    u64 pairs {W2[2jp][p], W2[2jp+1][p]} (pad jp=75 zero)
// b1s : [156]      (extra pad so jp2=38 prefetch stays in-bounds)
// W3t : [150][40]  transposed W3 rows (lane-distinct tail)
#define SM_W1N 0
#define SM_W2P 2736
#define SM_B1  3952
#define SM_W3T 4112
#define SM_B3  10112
#define SM_W4  10264
#define SM_B2  10416
#define SM_FLOATS 10424
#define SM_BYTES  (SM_FLOATS * 4)

// ---- per-group tail: warp stats over 32 lanes + group MLP (verified) -------
__device__ __noinline__ float group_tail(const float* a,
                                         const float* __restrict__ W3t,
                                         const float* __restrict__ b3s,
                                         const float* __restrict__ W4s,
                                         float b4v, int lane)
{
    u64 ag[20];   // packed agg pairs: ag[stat*4 + p/2] = {agg_p, agg_p+1}

    #pragma unroll
    for (int ph = 0; ph < 4; ++ph) {
        float va = a[2 * ph], vb = a[2 * ph + 1];

        // mean
        float sa = va, sb = vb;
        #pragma unroll
        for (int o = 16; o; o >>= 1) {
            sa += __shfl_xor_sync(0xffffffffu, sa, o);
            sb += __shfl_xor_sync(0xffffffffu, sb, o);
        }
        float meana = sa * (1.0f / 32.0f), meanb = sb * (1.0f / 32.0f);

        // unbiased variance (two-pass)
        float da = va - meana, db = vb - meanb;
        float qa = da * da, qb = db * db;
        #pragma unroll
        for (int o = 16; o; o >>= 1) {
            qa += __shfl_xor_sync(0xffffffffu, qa, o);
            qb += __shfl_xor_sync(0xffffffffu, qb, o);
        }
        float vara = qa * (1.0f / 31.0f), varb = qb * (1.0f / 31.0f);

        // min / max
        float mna = va, mxa = va, mnb = vb, mxb = vb;
        #pragma unroll
        for (int o = 16; o; o >>= 1) {
            mna = fminf(mna, __shfl_xor_sync(0xffffffffu, mna, o));
            mxa = fmaxf(mxa, __shfl_xor_sync(0xffffffffu, mxa, o));
            mnb = fminf(mnb, __shfl_xor_sync(0xffffffffu, mnb, o));
            mxb = fmaxf(mxb, __shfl_xor_sync(0xffffffffu, mxb, o));
        }

        // lower median via warp bitonic sort (two sorts interleaved)
        float ta = va, tb = vb;
        #pragma unroll
        for (int k = 2; k <= 32; k <<= 1) {
            #pragma unroll
            for (int j = k >> 1; j > 0; j >>= 1) {
                float oa = __shfl_xor_sync(0xffffffffu, ta, j);
                float ob = __shfl_xor_sync(0xffffffffu, tb, j);
                bool keep_lo = (((lane & j) == 0) == ((lane & k) == 0));
                float la = fminf(ta, oa), ha = fmaxf(ta, oa);
                float lb = fminf(tb, ob), hb = fmaxf(tb, ob);
                ta = keep_lo ? la : ha;
                tb = keep_lo ? lb : hb;
            }
        }
        float meda = __shfl_sync(0xffffffffu, ta, 15);
        float medb = __shfl_sync(0xffffffffu, tb, 15);

        ag[0 * 4 + ph] = pk2(meana, meanb);
        ag[1 * 4 + ph] = pk2(vara, varb);
        ag[2 * 4 + ph] = pk2(mna, mnb);
        ag[3 * 4 + ph] = pk2(meda, medb);
        ag[4 * 4 + ph] = pk2(mxa, mxb);
    }

    // group MLP: 40 -> 150 (relu) -> 1, hidden units strided over lanes
    float zp = 0.0f;
    #pragma unroll 1
    for (int j = lane; j < H1; j += 32) {
        const ulonglong2* wr = (const ulonglong2*)(W3t + j * 40);
        u64 t2a = 0ull, t2b = 0ull;
        #pragma unroll
        for (int q = 0; q < 10; ++q) {
            ulonglong2 w = wr[q];
            t2a = fma2(ag[2 * q],     w.x, t2a);
            t2b = fma2(ag[2 * q + 1], w.y, t2b);
        }
        float2 sa = upk2(t2a), sb = upk2(t2b);
        float t = (sa.x + sa.y) + (sb.x + sb.y) + b3s[j];
        t = fmaxf(t, 0.0f);
        zp = fmaf(t, W4s[j], zp);
    }
    #pragma unroll
    for (int o = 16; o; o >>= 1) zp += __shfl_xor_sync(0xffffffffu, zp, o);

    return 1.0f / (1.0f + __expf(-(zp + b4v)));
}

__global__ void __launch_bounds__(128, 3)
minn_fused_pipe_kernel(const float* __restrict__ x,
                       const int*   __restrict__ kmer,
                       const int*   __restrict__ indices,
                       const float* __restrict__ emb,
                       const float* __restrict__ W1, const float* __restrict__ b1,
                       const float* __restrict__ W2, const float* __restrict__ b2,
                       const float* __restrict__ W3, const float* __restrict__ b3,
                       const float* __restrict__ W4, const float* __restrict__ b4,
                       float* __restrict__ out)
{
    extern __shared__ float sm[];
    float* W1n  = sm + SM_W1N;
    u64*   W2pu = (u64*)(sm + SM_W2P);
    float* b1s  = sm + SM_B1;
    float* W3t  = sm + SM_W3T;
    float* b3s  = sm + SM_B3;
    float* W4s  = sm + SM_W4;
    float* b2s  = sm + SM_B2;

    const int tid = threadIdx.x;

    // ---- stage weights (natural layouts; no duplication anywhere) ----
    for (int i = tid; i < 18 * 152; i += 128) {
        int k = i / 152, j = i - k * 152;
        W1n[i] = (j < H1) ? W1[k * H1 + j] : 0.0f;
    }
    for (int i = tid; i < 76 * PP; i += 128) {
        int jp = i >> 3, p = i & 7;
        int j0 = 2 * jp, j1 = 2 * jp + 1;
        float w0 = (j0 < H1) ? W2[j0 * PP + p] : 0.0f;
        float w1 = (j1 < H1) ? W2[j1 * PP + p] : 0.0f;
        W2pu[i] = pk2(w0, w1);
    }
    for (int i = tid; i < 156; i += 128)
        b1s[i] = (i < H1) ? b1[i] : 0.0f;
    for (int i = tid; i < 40 * H1; i += 128) {
        int j = i / 40, k = i - j * 40;
        W3t[i] = W3[k * H1 + j];
    }
    for (int i = tid; i < H1; i += 128) {
        b3s[i] = b3[i];
        W4s[i] = W4[i];
    }
    if (tid < PP) b2s[tid] = b2[tid];
    const float b4v = __ldg(b4);
    __syncthreads();

    const int warp = tid >> 5;
    const int lane = tid & 31;
    const int g0 = (blockIdx.x * 4 + warp) * 4;   // 4 groups per warp

    // ---- gather the 4 reads this lane owns, packed read-pair-wise ----
    const int r0 = indices[(g0 + 0) * 32 + lane];
    const int r1 = indices[(g0 + 1) * 32 + lane];
    const int r2 = indices[(g0 + 2) * 32 + lane];
    const int r3 = indices[(g0 + 3) * 32 + lane];

    u64 rp0[18], rp1[18];   // rp0[k]={r0[k],r1[k]}, rp1[k]={r2[k],r3[k]}
    {
        const float4* p0 = (const float4*)(x + (size_t)r0 * 16);
        const float4* p1 = (const float4*)(x + (size_t)r1 * 16);
        const float4* p2 = (const float4*)(x + (size_t)r2 * 16);
        const float4* p3 = (const float4*)(x + (size_t)r3 * 16);
        #pragma unroll
        for (int q = 0; q < 4; ++q) {
            float4 v0 = p0[q], v1 = p1[q], v2 = p2[q], v3 = p3[q];
            rp0[4 * q + 0] = pk2(v0.x, v1.x);  rp1[4 * q + 0] = pk2(v2.x, v3.x);
            rp0[4 * q + 1] = pk2(v0.y, v1.y);  rp1[4 * q + 1] = pk2(v2.y, v3.y);
            rp0[4 * q + 2] = pk2(v0.z, v1.z);  rp1[4 * q + 2] = pk2(v2.z, v3.z);
            rp0[4 * q + 3] = pk2(v0.w, v1.w);  rp1[4 * q + 3] = pk2(v2.w, v3.w);
        }
        float2 e0 = ((const float2*)emb)[kmer[r0]];
        float2 e1 = ((const float2*)emb)[kmer[r1]];
        float2 e2 = ((const float2*)emb)[kmer[r2]];
        float2 e3 = ((const float2*)emb)[kmer[r3]];
        rp0[16] = pk2(e0.x, e1.x);  rp1[16] = pk2(e2.x, e3.x);
        rp0[17] = pk2(e0.y, e1.y);  rp1[17] = pk2(e2.y, e3.y);
    }

    // ---- per-read MLP via diagonal f32x2, software-pipelined jp2 loop ----
    u64 ACC0[PP], ACC1[PP];
    #pragma unroll
    for (int p = 0; p < PP; ++p) { ACC0[p] = 0ull; ACC1[p] = 0ull; }

    // prologue: prime the 4-deep W1 ring + b quad for jp2=0
    float4 wf0, wf1, wf2, wf3, bq;
    {
        const float* w1c = W1n;
        wf0 = *(const float4*)(w1c + 0 * 152);
        wf1 = *(const float4*)(w1c + 1 * 152);
        wf2 = *(const float4*)(w1c + 2 * 152);
        wf3 = *(const float4*)(w1c + 3 * 152);
        bq  = *(const float4*)(b1s);
    }

    #pragma unroll 1
    for (int jp2 = 0; jp2 < 38; ++jp2) {
        // W2 loads issue first; consumed at the END of this iteration
        ulonglong2 w2a0, w2a1, w2a2, w2a3, w2b0, w2b1, w2b2, w2b3;
        {
            const ulonglong2* w2a = (const ulonglong2*)(W2pu + (2 * jp2) * PP);
            const ulonglong2* w2b = (const ulonglong2*)(W2pu + (2 * jp2 + 1) * PP);
            w2a0 = w2a[0]; w2a1 = w2a[1]; w2a2 = w2a[2]; w2a3 = w2a[3];
            w2b0 = w2b[0]; w2b1 = w2b[1]; w2b2 = w2b[2]; w2b3 = w2b[3];
        }

        u64 BpA = pk2(bq.x, bq.y), BsA = pk2(bq.y, bq.x);
        u64 BpB = pk2(bq.z, bq.w), BsB = pk2(bq.w, bq.z);
        u64 A00 = BpA, A01 = BsA, A10 = BpA, A11 = BsA;
        u64 C00 = BpB, C01 = BsB, C10 = BpB, C11 = BsB;

        const float* w1c = W1n + 4 * jp2;

        // k-loop with 4-deep rolling ring: load k+4 while computing k
        #pragma unroll
        for (int k = 0; k < 18; ++k) {
            float4 wq;
            switch (k & 3) {
                case 0: wq = wf0; break;
                case 1: wq = wf1; break;
                case 2: wq = wf2; break;
                default: wq = wf3; break;
            }
            if (k + 4 < 18) {
                float4 nxt = *(const float4*)(w1c + (k + 4) * 152);
                switch (k & 3) {
                    case 0: wf0 = nxt; break;
                    case 1: wf1 = nxt; break;
                    case 2: wf2 = nxt; break;
                    default: wf3 = nxt; break;
                }
            }
            u64 wpA = pk2(wq.x, wq.y), wsA = pk2(wq.y, wq.x);
            u64 wpB = pk2(wq.z, wq.w), wsB = pk2(wq.w, wq.z);
            A00 = fma2(rp0[k], wpA, A00);
            A01 = fma2(rp0[k], wsA, A01);
            A10 = fma2(rp1[k], wpA, A10);
            A11 = fma2(rp1[k], wsA, A11);
            C00 = fma2(rp0[k], wpB, C00);
            C01 = fma2(rp0[k], wsB, C01);
            C10 = fma2(rp1[k], wpB, C10);
            C11 = fma2(rp1[k], wsB, C11);
        }

        // ring is dead now: refill with NEXT iteration's k=0..3 + b quad,
        // hidden under the relu + W2 phase below (~130 issue cycles)
        {
            const float* w1nx = W1n + 4 * (jp2 + 1);
            // jp2=37: reads row 152 of W1n... guard with min to stay in-bounds
            const float* w1safe = (jp2 + 1 < 38) ? w1nx : W1n;
            wf0 = *(const float4*)(w1safe + 0 * 152);
            wf1 = *(const float4*)(w1safe + 1 * 152);
            wf2 = *(const float4*)(w1safe + 2 * 152);
            wf3 = *(const float4*)(w1safe + 3 * 152);
            bq  = *(const float4*)(b1s + 4 * ((jp2 + 1 < 38) ? jp2 + 1 : 0));
        }

        A00 = relu2(A00);  A01 = relu2(A01);
        A10 = relu2(A10);  A11 = relu2(A11);
        C00 = relu2(C00);  C01 = relu2(C01);
        C10 = relu2(C10);  C11 = relu2(C11);

        #pragma unroll
        for (int q = 0; q < 4; ++q) {
            ulonglong2 wa = (q == 0) ? w2a0 : (q == 1) ? w2a1 : (q == 2) ? w2a2 : w2a3;
            ulonglong2 wb = (q == 0) ? w2b0 : (q == 1) ? w2b1 : (q == 2) ? w2b2 : w2b3;
            float2 wa0 = upk2(wa.x), wa1 = upk2(wa.y);
            float2 wb0 = upk2(wb.x), wb1 = upk2(wb.y);
            u64 wap0 = pk2(wa0.x, wa0.y), was0 = pk2(wa0.y, wa0.x);
            u64 wap1 = pk2(wa1.x, wa1.y), was1 = pk2(wa1.y, wa1.x);
            u64 wbp0 = pk2(wb0.x, wb0.y), wbs0 = pk2(wb0.y, wb0.x);
            u64 wbp1 = pk2(wb1.x, wb1.y), wbs1 = pk2(wb1.y, wb1.x);

            ACC0[2 * q]     = fma2(A00, wap0, ACC0[2 * q]);
            ACC0[2 * q]     = fma2(A01, was0, ACC0[2 * q]);
            ACC0[2 * q]     = fma2(C00, wbp0, ACC0[2 * q]);
            ACC0[2 * q]     = fma2(C01, wbs0, ACC0[2 * q]);
            ACC0[2 * q + 1] = fma2(A00, wap1, ACC0[2 * q + 1]);
            ACC0[2 * q + 1] = fma2(A01, was1, ACC0[2 * q + 1]);
            ACC0[2 * q + 1] = fma2(C00, wbp1, ACC0[2 * q + 1]);
            ACC0[2 * q + 1] = fma2(C01, wbs1, ACC0[2 * q + 1]);

            ACC1[2 * q]     = fma2(A10, wap0, ACC1[2 * q]);
            ACC1[2 * q]     = fma2(A11, was0, ACC1[2 * q]);
            ACC1[2 * q]     = fma2(C10, wbp0, ACC1[2 * q]);
            ACC1[2 * q]     = fma2(C11, wbs0, ACC1[2 * q]);
            ACC1[2 * q + 1] = fma2(A10, wap1, ACC1[2 * q + 1]);
            ACC1[2 * q + 1] = fma2(A11, was1, ACC1[2 * q + 1]);
            ACC1[2 * q + 1] = fma2(C10, wbp1, ACC1[2 * q + 1]);
            ACC1[2 * q + 1] = fma2(C11, wbs1, ACC1[2 * q + 1]);
        }
    }

    // add b2, final relu, unpack per-group activations
    float s0[PP], s1[PP], s2[PP], s3[PP];
    #pragma unroll
    for (int p = 0; p < PP; ++p) {
        float bp = b2s[p];
        float2 t = upk2(ACC0[p]);
        s0[p] = fmaxf(t.x + bp, 0.0f);
        s1[p] = fmaxf(t.y + bp, 0.0f);
        float2 u = upk2(ACC1[p]);
        s2[p] = fmaxf(u.x + bp, 0.0f);
        s3[p] = fmaxf(u.y + bp, 0.0f);
    }

    // ---- per-group aggregation + group MLP ----
    float o0 = group_tail(s0, W3t, b3s, W4s, b4v, lane);
    if (lane == 0) out[g0 + 0] = o0;
    float o1 = group_tail(s1, W3t, b3s, W4s, b4v, lane);
    if (lane == 0) out[g0 + 1] = o1;
    float o2 = group_tail(s2, W3t, b3s, W4s, b4v, lane);
    if (lane == 0) out[g0 + 2] = o2;
    float o3 = group_tail(s3, W3t, b3s, W4s, b4v, lane);
    if (lane == 0) out[g0 + 3] = o3;
}

extern "C" void kernel_launch(void* const* d_in, const int* in_sizes, int n_in,
                              void* d_out, int out_size)
{
    const float* x       = (const float*)d_in[0];
    const int*   kmer    = (const int*)  d_in[1];
    const int*   indices = (const int*)  d_in[2];
    const float* emb     = (const float*)d_in[3];
    const float* W1      = (const float*)d_in[4];
    const float* b1      = (const float*)d_in[5];
    const float* W2      = (const float*)d_in[6];
    const float* b2      = (const float*)d_in[7];
    const float* W3      = (const float*)d_in[8];
    const float* b3      = (const float*)d_in[9];
    const float* W4      = (const float*)d_in[10];
    const float* b4      = (const float*)d_in[11];
    float* out = (float*)d_out;

    cudaFuncSetAttribute(minn_fused_pipe_kernel,
                         cudaFuncAttributeMaxDynamicSharedMemorySize, SM_BYTES);

    // 4 warps/block * 4 groups/warp = 16 groups per block
    const int blocks = G_TOTAL / 16;   // 2048
    minn_fused_pipe_kernel<<<blocks, 128, SM_BYTES>>>(
        x, kmer, indices, emb, W1, b1, W2, b2, W3, b3, W4, b4, out);
}

// round 12
// speedup vs baseline: 1.3520x; 1.1747x over previous
#include <cuda_runtime.h>

#define G_TOTAL 32768
#define H1      150
#define PP      8

using u64 = unsigned long long;
using u32 = unsigned int;

// ---- packed f32x2 helpers (verified) ----------------------------------------
__device__ __forceinline__ u64 pk2(float a, float b) {
    u64 r;
    asm("mov.b64 %0,{%1,%2};" : "=l"(r)
        : "r"(__float_as_uint(a)), "r"(__float_as_uint(b)));
    return r;
}
__device__ __forceinline__ float2 upk2(u64 v) {
    unsigned lo, hi;
    asm("mov.b64 {%0,%1},%2;" : "=r"(lo), "=r"(hi) : "l"(v));
    return make_float2(__uint_as_float(lo), __uint_as_float(hi));
}
__device__ __forceinline__ u64 fma2(u64 a, u64 b, u64 c) {
    u64 d;
    asm("fma.rn.f32x2 %0,%1,%2,%3;" : "=l"(d) : "l"(a), "l"(b), "l"(c));
    return d;
}

// ---- bf16 / mma helpers ------------------------------------------------------
// pack {hi, lo} floats into bf16x2 (lo in low 16 bits)
__device__ __forceinline__ u32 cvtbf2(float hi, float lo) {
    u32 d;
    asm("cvt.rn.bf16x2.f32 %0,%1,%2;" : "=r"(d) : "f"(hi), "f"(lo));
    return d;
}
__device__ __forceinline__ void mma16816(float& d0, float& d1, float& d2, float& d3,
                                         u32 a0, u32 a1, u32 a2, u32 a3,
                                         u32 b0, u32 b1,
                                         float c0, float c1, float c2, float c3)
{
    asm volatile("mma.sync.aligned.m16n8k16.row.col.f32.bf16.bf16.f32 "
                 "{%0,%1,%2,%3},{%4,%5,%6,%7},{%8,%9},{%10,%11,%12,%13};"
                 : "=f"(d0), "=f"(d1), "=f"(d2), "=f"(d3)
                 : "r"(a0), "r"(a1), "r"(a2), "r"(a3), "r"(b0), "r"(b1),
                   "f"(c0), "f"(c1), "f"(c2), "f"(c3));
}

// ---- shared-memory layout (float offsets) ------------------------------------
// W1T : [160 j][32 k] bf16  (j,k zero-padded)        2560 floats
// W2T : [8 p][160 j] bf16   (j zero-padded)           640 floats
// b1f : [160] f32                                     160
// b2f : [8] f32                                       8
// b3s : [152] f32                                     152
// W4s : [152] f32                                     152
// W3t : [150][40] f32 transposed                      6000
// inb : 4 warps x 128 rows x 64B (bf16 inputs)        8192 floats
//       (first 4096 B of each warp slice is reused as aw[128][8] f32)
#define SM_W1T 0
#define SM_W2T 2560
#define SM_B1F 3200
#define SM_B2F 3360
#define SM_B3  3368
#define SM_W4  3520
#define SM_W3T 3672
#define SM_INB 9672
#define SM_FLOATS (9672 + 8192)
#define SM_BYTES  (SM_FLOATS * 4)

// ---- per-group tail: warp stats over 32 lanes + group MLP (verified) -------
__device__ __noinline__ float group_tail(const float* a,
                                         const float* __restrict__ W3t,
                                         const float* __restrict__ b3s,
                                         const float* __restrict__ W4s,
                                         float b4v, int lane)
{
    u64 ag[20];   // packed agg pairs: ag[stat*4 + p/2] = {agg_p, agg_p+1}

    #pragma unroll
    for (int ph = 0; ph < 4; ++ph) {
        float va = a[2 * ph], vb = a[2 * ph + 1];

        // mean
        float sa = va, sb = vb;
        #pragma unroll
        for (int o = 16; o; o >>= 1) {
            sa += __shfl_xor_sync(0xffffffffu, sa, o);
            sb += __shfl_xor_sync(0xffffffffu, sb, o);
        }
        float meana = sa * (1.0f / 32.0f), meanb = sb * (1.0f / 32.0f);

        // unbiased variance (two-pass)
        float da = va - meana, db = vb - meanb;
        float qa = da * da, qb = db * db;
        #pragma unroll
        for (int o = 16; o; o >>= 1) {
            qa += __shfl_xor_sync(0xffffffffu, qa, o);
            qb += __shfl_xor_sync(0xffffffffu, qb, o);
        }
        float vara = qa * (1.0f / 31.0f), varb = qb * (1.0f / 31.0f);

        // min / max
        float mna = va, mxa = va, mnb = vb, mxb = vb;
        #pragma unroll
        for (int o = 16; o; o >>= 1) {
            mna = fminf(mna, __shfl_xor_sync(0xffffffffu, mna, o));
            mxa = fmaxf(mxa, __shfl_xor_sync(0xffffffffu, mxa, o));
            mnb = fminf(mnb, __shfl_xor_sync(0xffffffffu, mnb, o));
            mxb = fmaxf(mxb, __shfl_xor_sync(0xffffffffu, mxb, o));
        }

        // lower median via warp bitonic sort (two sorts interleaved)
        float ta = va, tb = vb;
        #pragma unroll
        for (int k = 2; k <= 32; k <<= 1) {
            #pragma unroll
            for (int j = k >> 1; j > 0; j >>= 1) {
                float oa = __shfl_xor_sync(0xffffffffu, ta, j);
                float ob = __shfl_xor_sync(0xffffffffu, tb, j);
                bool keep_lo = (((lane & j) == 0) == ((lane & k) == 0));
                float la = fminf(ta, oa), ha = fmaxf(ta, oa);
                float lb = fminf(tb, ob), hb = fmaxf(tb, ob);
                ta = keep_lo ? la : ha;
                tb = keep_lo ? lb : hb;
            }
        }
        float meda = __shfl_sync(0xffffffffu, ta, 15);
        float medb = __shfl_sync(0xffffffffu, tb, 15);

        ag[0 * 4 + ph] = pk2(meana, meanb);
        ag[1 * 4 + ph] = pk2(vara, varb);
        ag[2 * 4 + ph] = pk2(mna, mnb);
        ag[3 * 4 + ph] = pk2(meda, medb);
        ag[4 * 4 + ph] = pk2(mxa, mxb);
    }

    // group MLP: 40 -> 150 (relu) -> 1, hidden units strided over lanes
    float zp = 0.0f;
    #pragma unroll 1
    for (int j = lane; j < H1; j += 32) {
        const ulonglong2* wr = (const ulonglong2*)(W3t + j * 40);
        u64 t2a = 0ull, t2b = 0ull;
        #pragma unroll
        for (int q = 0; q < 10; ++q) {
            ulonglong2 w = wr[q];
            t2a = fma2(ag[2 * q],     w.x, t2a);
            t2b = fma2(ag[2 * q + 1], w.y, t2b);
        }
        float2 sa = upk2(t2a), sb = upk2(t2b);
        float t = (sa.x + sa.y) + (sb.x + sb.y) + b3s[j];
        t = fmaxf(t, 0.0f);
        zp = fmaf(t, W4s[j], zp);
    }
    #pragma unroll
    for (int o = 16; o; o >>= 1) zp += __shfl_xor_sync(0xffffffffu, zp, o);

    return 1.0f / (1.0f + __expf(-(zp + b4v)));
}

__global__ void __launch_bounds__(128, 3)
minn_fused_mma_kernel(const float* __restrict__ x,
                      const int*   __restrict__ kmer,
                      const int*   __restrict__ indices,
                      const float* __restrict__ emb,
                      const float* __restrict__ W1, const float* __restrict__ b1,
                      const float* __restrict__ W2, const float* __restrict__ b2,
                      const float* __restrict__ W3, const float* __restrict__ b3,
                      const float* __restrict__ W4, const float* __restrict__ b4,
                      float* __restrict__ out)
{
    extern __shared__ float sm[];
    u32*   W1T = (u32*)(sm + SM_W1T);    // [160][16] u32 of bf16x2 (k-pairs)
    u32*   W2T = (u32*)(sm + SM_W2T);    // [8][80]  u32 of bf16x2 (j-pairs)
    float* b1f = sm + SM_B1F;
    float* b2f = sm + SM_B2F;
    float* b3s = sm + SM_B3;
    float* W4s = sm + SM_W4;
    float* W3t = sm + SM_W3T;

    const int tid = threadIdx.x;

    // ---- stage weight tables (block-cooperative) ----
    // W1T[j][kpair]: bf16x2 {W1[2kp][j], W1[2kp+1][j]}, zero outside 18k/150j
    for (int i = tid; i < 160 * 16; i += 128) {
        int j = i >> 4, kp = i & 15;
        int k0 = 2 * kp, k1 = 2 * kp + 1;
        float w0 = (j < H1 && k0 < 18) ? W1[k0 * H1 + j] : 0.0f;
        float w1 = (j < H1 && k1 < 18) ? W1[k1 * H1 + j] : 0.0f;
        W1T[i] = cvtbf2(w1, w0);
    }
    // W2T[p][jpair]: bf16x2 {W2[2jp][p], W2[2jp+1][p]}
    for (int i = tid; i < 8 * 80; i += 128) {
        int p = i / 80, jp = i - p * 80;
        int j0 = 2 * jp, j1 = j0 + 1;
        float w0 = (j0 < H1) ? W2[j0 * PP + p] : 0.0f;
        float w1 = (j1 < H1) ? W2[j1 * PP + p] : 0.0f;
        W2T[i] = cvtbf2(w1, w0);
    }
    for (int i = tid; i < 160; i += 128) b1f[i] = (i < H1) ? b1[i] : 0.0f;
    if (tid < PP) b2f[tid] = b2[tid];
    for (int i = tid; i < 40 * H1; i += 128) {
        int j = i / 40, k = i - j * 40;
        W3t[i] = W3[k * H1 + j];
    }
    for (int i = tid; i < 152; i += 128) {
        b3s[i] = (i < H1) ? b3[i] : 0.0f;
        W4s[i] = (i < H1) ? W4[i] : 0.0f;
    }
    const float b4v = __ldg(b4);
    __syncthreads();

    const int warp = tid >> 5;
    const int lane = tid & 31;
    const int g0 = (blockIdx.x * 4 + warp) * 4;   // 4 groups per warp
    const int lq = lane >> 2;                      // groupID (0..7)
    const int lc = lane & 3;                       // thread-in-group (0..3)

    char* inbw = (char*)(sm + SM_INB) + warp * 8192;   // 128 rows x 64 B bf16
    char* aw   = inbw;                                 // overlay: 128 x 32 B f32

    // ---- stage this warp's 128 reads as bf16 rows [r][32k] ----
    #pragma unroll
    for (int i = 0; i < 4; ++i) {
        const int r = indices[(g0 + i) * 32 + lane];
        const float4* px = (const float4*)(x + (size_t)r * 16);
        float4 v0 = px[0], v1 = px[1], v2 = px[2], v3 = px[3];
        float2 e = ((const float2*)emb)[kmer[r]];
        u32 row[16];
        row[0] = cvtbf2(v0.y, v0.x);  row[1] = cvtbf2(v0.w, v0.z);
        row[2] = cvtbf2(v1.y, v1.x);  row[3] = cvtbf2(v1.w, v1.z);
        row[4] = cvtbf2(v2.y, v2.x);  row[5] = cvtbf2(v2.w, v2.z);
        row[6] = cvtbf2(v3.y, v3.x);  row[7] = cvtbf2(v3.w, v3.z);
        row[8] = cvtbf2(e.y, e.x);
        #pragma unroll
        for (int q = 9; q < 16; ++q) row[q] = 0u;
        uint4* dst = (uint4*)(inbw + (i * 32 + lane) * 64);
        dst[0] = make_uint4(row[0], row[1], row[2], row[3]);
        dst[1] = make_uint4(row[4], row[5], row[6], row[7]);
        dst[2] = make_uint4(row[8], row[9], row[10], row[11]);
        dst[3] = make_uint4(row[12], row[13], row[14], row[15]);
    }
    __syncwarp();

    const float2 b2p = *(const float2*)(b2f + 2 * lc);

    // ---- two passes of 64 reads: GEMM1 (in x W1, relu) chained into GEMM2 ----
    #pragma unroll 1
    for (int pass = 0; pass < 2; ++pass) {
        // load A fragments for 4 m-tiles (rows pass*64 + m*16 .. +15)
        u32 Af[4][8];
        #pragma unroll
        for (int m = 0; m < 4; ++m) {
            const char* base = inbw + (pass * 64 + m * 16 + lq) * 64 + lc * 4;
            Af[m][0] = *(const u32*)(base);
            Af[m][1] = *(const u32*)(base + 8 * 64);
            Af[m][2] = *(const u32*)(base + 16);
            Af[m][3] = *(const u32*)(base + 8 * 64 + 16);
            Af[m][4] = *(const u32*)(base + 32);
            Af[m][5] = *(const u32*)(base + 8 * 64 + 32);
            Af[m][6] = *(const u32*)(base + 48);
            Af[m][7] = *(const u32*)(base + 8 * 64 + 48);
        }

        float C2[4][4];
        #pragma unroll
        for (int m = 0; m < 4; ++m)
            C2[m][0] = C2[m][1] = C2[m][2] = C2[m][3] = 0.0f;

        u32 a2f[4][4];

        #pragma unroll 1
        for (int t = 0; t < 10; ++t) {
            // ---- n = 2t (even): fills a2f[..][0,1] ----
            #pragma unroll
            for (int half = 0; half < 2; ++half) {
                const int n = 2 * t + half;
                const int j = 8 * n + lq;
                const char* wb = (const char*)W1T + j * 64 + lc * 4;
                u32 b00 = *(const u32*)(wb);
                u32 b01 = *(const u32*)(wb + 16);
                u32 b10 = *(const u32*)(wb + 32);
                u32 b11 = *(const u32*)(wb + 48);
                float2 b1p = *(const float2*)(b1f + 8 * n + 2 * lc);
                #pragma unroll
                for (int m = 0; m < 4; ++m) {
                    float c0, c1, c2, c3;
                    mma16816(c0, c1, c2, c3,
                             Af[m][0], Af[m][1], Af[m][2], Af[m][3],
                             b00, b01, 0.0f, 0.0f, 0.0f, 0.0f);
                    mma16816(c0, c1, c2, c3,
                             Af[m][4], Af[m][5], Af[m][6], Af[m][7],
                             b10, b11, c0, c1, c2, c3);
                    float h0 = fmaxf(c0 + b1p.x, 0.0f);
                    float h1 = fmaxf(c1 + b1p.y, 0.0f);
                    float h2 = fmaxf(c2 + b1p.x, 0.0f);
                    float h3 = fmaxf(c3 + b1p.y, 0.0f);
                    a2f[m][2 * half]     = cvtbf2(h1, h0);
                    a2f[m][2 * half + 1] = cvtbf2(h3, h2);
                }
            }
            // ---- fold j-block of 16 into GEMM2 accumulators ----
            {
                const char* w2b = (const char*)W2T + lq * 320 + (16 * t + 2 * lc) * 2;
                u32 w20 = *(const u32*)(w2b);
                u32 w21 = *(const u32*)(w2b + 16);
                #pragma unroll
                for (int m = 0; m < 4; ++m) {
                    mma16816(C2[m][0], C2[m][1], C2[m][2], C2[m][3],
                             a2f[m][0], a2f[m][1], a2f[m][2], a2f[m][3],
                             w20, w21,
                             C2[m][0], C2[m][1], C2[m][2], C2[m][3]);
                }
            }
        }

        // ---- a = relu(C2 + b2), write to aw[r][p] (overlay on consumed inb) ----
        #pragma unroll
        for (int m = 0; m < 4; ++m) {
            int rb = pass * 64 + m * 16 + lq;
            float2 lo = make_float2(fmaxf(C2[m][0] + b2p.x, 0.0f),
                                    fmaxf(C2[m][1] + b2p.y, 0.0f));
            float2 hi = make_float2(fmaxf(C2[m][2] + b2p.x, 0.0f),
                                    fmaxf(C2[m][3] + b2p.y, 0.0f));
            *(float2*)(aw + rb * 32 + lc * 8)       = lo;
            *(float2*)(aw + (rb + 8) * 32 + lc * 8) = hi;
        }
    }
    __syncwarp();

    // ---- per-group aggregation + group MLP (verified tail) ----
    #pragma unroll 1
    for (int i = 0; i < 4; ++i) {
        float4 qa = *(const float4*)(aw + (i * 32 + lane) * 32);
        float4 qb = *(const float4*)(aw + (i * 32 + lane) * 32 + 16);
        float s[PP] = {qa.x, qa.y, qa.z, qa.w, qb.x, qb.y, qb.z, qb.w};
        float o = group_tail(s, W3t, b3s, W4s, b4v, lane);
        if (lane == 0) out[g0 + i] = o;
    }
}

extern "C" void kernel_launch(void* const* d_in, const int* in_sizes, int n_in,
                              void* d_out, int out_size)
{
    const float* x       = (const float*)d_in[0];
    const int*   kmer    = (const int*)  d_in[1];
    const int*   indices = (const int*)  d_in[2];
    const float* emb     = (const float*)d_in[3];
    const float* W1      = (const float*)d_in[4];
    const float* b1      = (const float*)d_in[5];
    const float* W2      = (const float*)d_in[6];
    const float* b2      = (const float*)d_in[7];
    const float* W3      = (const float*)d_in[8];
    const float* b3      = (const float*)d_in[9];
    const float* W4      = (const float*)d_in[10];
    const float* b4      = (const float*)d_in[11];
    float* out = (float*)d_out;

    cudaFuncSetAttribute(minn_fused_mma_kernel,
                         cudaFuncAttributeMaxDynamicSharedMemorySize, SM_BYTES);

    // 4 warps/block * 4 groups/warp = 16 groups per block
    const int blocks = G_TOTAL / 16;   // 2048
    minn_fused_mma_kernel<<<blocks, 128, SM_BYTES>>>(
        x, kmer, indices, emb, W1, b1, W2, b2, W3, b3, W4, b4, out);
}

// round 13
// speedup vs baseline: 1.8148x; 1.3423x over previous
#include <cuda_runtime.h>

#define G_TOTAL 32768
#define H1      150
#define PP      8

using u64 = unsigned long long;
using u32 = unsigned int;

// ---- packed f32x2 helpers (verified) ----------------------------------------
__device__ __forceinline__ u64 pk2(float a, float b) {
    u64 r;
    asm("mov.b64 %0,{%1,%2};" : "=l"(r)
        : "r"(__float_as_uint(a)), "r"(__float_as_uint(b)));
    return r;
}
__device__ __forceinline__ float2 upk2(u64 v) {
    unsigned lo, hi;
    asm("mov.b64 {%0,%1},%2;" : "=r"(lo), "=r"(hi) : "l"(v));
    return make_float2(__uint_as_float(lo), __uint_as_float(hi));
}
__device__ __forceinline__ u64 fma2(u64 a, u64 b, u64 c) {
    u64 d;
    asm("fma.rn.f32x2 %0,%1,%2,%3;" : "=l"(d) : "l"(a), "l"(b), "l"(c));
    return d;
}

// ---- bf16 / mma helpers ------------------------------------------------------
__device__ __forceinline__ u32 cvtbf2(float hi, float lo) {
    u32 d;
    asm("cvt.rn.bf16x2.f32 %0,%1,%2;" : "=r"(d) : "f"(hi), "f"(lo));
    return d;
}
__device__ __forceinline__ void mma16816(float& d0, float& d1, float& d2, float& d3,
                                         u32 a0, u32 a1, u32 a2, u32 a3,
                                         u32 b0, u32 b1,
                                         float c0, float c1, float c2, float c3)
{
    asm volatile("mma.sync.aligned.m16n8k16.row.col.f32.bf16.bf16.f32 "
                 "{%0,%1,%2,%3},{%4,%5,%6,%7},{%8,%9},{%10,%11,%12,%13};"
                 : "=f"(d0), "=f"(d1), "=f"(d2), "=f"(d3)
                 : "r"(a0), "r"(a1), "r"(a2), "r"(a3), "r"(b0), "r"(b1),
                   "f"(c0), "f"(c1), "f"(c2), "f"(c3));
}

// ---- shared-memory layout (float offsets) ------------------------------------
// W1T : [160 j][32 k] bf16, 16B-chunk-swizzled rows   2560 floats
// W2T : [8 p][160 j] bf16                              640
// b1f : [160] f32                                      160
// b2f : [8] f32                                        8
// b3s : [152] f32                                      152
// W4s : [152] f32                                      152
// W3q : [10 q][152 j][4] f32 (tail, contiguous in j)   6080
// inb : 4 warps x 128 rows x 64B bf16, swizzled        8192
//       (first 4096 B of each warp slice reused as aw[128][32B], 1-bit swz)
#define SM_W1T 0
#define SM_W2T 2560
#define SM_B1F 3200
#define SM_B2F 3360
#define SM_B3  3368
#define SM_W4  3520
#define SM_W3Q 3672
#define SM_INB 9752
#define SM_FLOATS (9752 + 8192)
#define SM_BYTES  (SM_FLOATS * 4)

// ---- per-group tail: warp stats over 32 lanes + group MLP (verified math) ---
__device__ __noinline__ float group_tail(const float* a,
                                         const float* __restrict__ W3q,
                                         const float* __restrict__ b3s,
                                         const float* __restrict__ W4s,
                                         float b4v, int lane)
{
    u64 ag[20];   // packed agg pairs: ag[stat*4 + p/2] = {agg_p, agg_p+1}

    #pragma unroll
    for (int ph = 0; ph < 4; ++ph) {
        float va = a[2 * ph], vb = a[2 * ph + 1];

        // mean
        float sa = va, sb = vb;
        #pragma unroll
        for (int o = 16; o; o >>= 1) {
            sa += __shfl_xor_sync(0xffffffffu, sa, o);
            sb += __shfl_xor_sync(0xffffffffu, sb, o);
        }
        float meana = sa * (1.0f / 32.0f), meanb = sb * (1.0f / 32.0f);

        // unbiased variance (two-pass)
        float da = va - meana, db = vb - meanb;
        float qa = da * da, qb = db * db;
        #pragma unroll
        for (int o = 16; o; o >>= 1) {
            qa += __shfl_xor_sync(0xffffffffu, qa, o);
            qb += __shfl_xor_sync(0xffffffffu, qb, o);
        }
        float vara = qa * (1.0f / 31.0f), varb = qb * (1.0f / 31.0f);

        // min / max
        float mna = va, mxa = va, mnb = vb, mxb = vb;
        #pragma unroll
        for (int o = 16; o; o >>= 1) {
            mna = fminf(mna, __shfl_xor_sync(0xffffffffu, mna, o));
            mxa = fmaxf(mxa, __shfl_xor_sync(0xffffffffu, mxa, o));
            mnb = fminf(mnb, __shfl_xor_sync(0xffffffffu, mnb, o));
            mxb = fmaxf(mxb, __shfl_xor_sync(0xffffffffu, mxb, o));
        }

        // lower median via warp bitonic sort (two sorts interleaved)
        float ta = va, tb = vb;
        #pragma unroll
        for (int k = 2; k <= 32; k <<= 1) {
            #pragma unroll
            for (int j = k >> 1; j > 0; j >>= 1) {
                float oa = __shfl_xor_sync(0xffffffffu, ta, j);
                float ob = __shfl_xor_sync(0xffffffffu, tb, j);
                bool keep_lo = (((lane & j) == 0) == ((lane & k) == 0));
                float la = fminf(ta, oa), ha = fmaxf(ta, oa);
                float lb = fminf(tb, ob), hb = fmaxf(tb, ob);
                ta = keep_lo ? la : ha;
                tb = keep_lo ? lb : hb;
            }
        }
        float meda = __shfl_sync(0xffffffffu, ta, 15);
        float medb = __shfl_sync(0xffffffffu, tb, 15);

        ag[0 * 4 + ph] = pk2(meana, meanb);
        ag[1 * 4 + ph] = pk2(vara, varb);
        ag[2 * 4 + ph] = pk2(mna, mnb);
        ag[3 * 4 + ph] = pk2(meda, medb);
        ag[4 * 4 + ph] = pk2(mxa, mxb);
    }

    // group MLP: 40 -> 150 (relu) -> 1; W3q[q][j][4] is contiguous in j so
    // each LDS.128 is a 512B conflict-free warp access
    float zp = 0.0f;
    #pragma unroll 1
    for (int j = lane; j < H1; j += 32) {
        u64 t2a = 0ull, t2b = 0ull;
        #pragma unroll
        for (int q = 0; q < 10; ++q) {
            ulonglong2 w = *(const ulonglong2*)(W3q + (q * 152 + j) * 4);
            t2a = fma2(ag[2 * q],     w.x, t2a);
            t2b = fma2(ag[2 * q + 1], w.y, t2b);
        }
        float2 sa = upk2(t2a), sb = upk2(t2b);
        float t = (sa.x + sa.y) + (sb.x + sb.y) + b3s[j];
        t = fmaxf(t, 0.0f);
        zp = fmaf(t, W4s[j], zp);
    }
    #pragma unroll
    for (int o = 16; o; o >>= 1) zp += __shfl_xor_sync(0xffffffffu, zp, o);

    return 1.0f / (1.0f + __expf(-(zp + b4v)));
}

__global__ void __launch_bounds__(128, 3)
minn_fused_mma2_kernel(const float* __restrict__ x,
                       const int*   __restrict__ kmer,
                       const int*   __restrict__ indices,
                       const float* __restrict__ emb,
                       const float* __restrict__ W1, const float* __restrict__ b1,
                       const float* __restrict__ W2, const float* __restrict__ b2,
                       const float* __restrict__ W3, const float* __restrict__ b3,
                       const float* __restrict__ W4, const float* __restrict__ b4,
                       float* __restrict__ out)
{
    extern __shared__ float sm[];
    u32*   W1T = (u32*)(sm + SM_W1T);
    u32*   W2T = (u32*)(sm + SM_W2T);
    float* b1f = sm + SM_B1F;
    float* b2f = sm + SM_B2F;
    float* b3s = sm + SM_B3;
    float* W4s = sm + SM_W4;
    float* W3q = sm + SM_W3Q;

    const int tid = threadIdx.x;

    // ---- stage weight tables (block-cooperative) ----
    // W1T[j]: 16 u32 (bf16x2 k-pairs), 16B chunk index XOR-swizzled by (j>>1)&3
    for (int i = tid; i < 160 * 16; i += 128) {
        int j = i >> 4, kp = i & 15;
        int k0 = 2 * kp, k1 = 2 * kp + 1;
        float w0 = (j < H1 && k0 < 18) ? W1[k0 * H1 + j] : 0.0f;
        float w1 = (j < H1 && k1 < 18) ? W1[k1 * H1 + j] : 0.0f;
        int chunk = kp >> 2, e = kp & 3;
        int sw = (j >> 1) & 3;
        W1T[j * 16 + ((chunk ^ sw) << 2) + e] = cvtbf2(w1, w0);
    }
    // W2T[p][jpair]: bf16x2 {W2[2jp][p], W2[2jp+1][p]} (no swizzle needed)
    for (int i = tid; i < 8 * 80; i += 128) {
        int p = i / 80, jp = i - p * 80;
        int j0 = 2 * jp, j1 = j0 + 1;
        float w0 = (j0 < H1) ? W2[j0 * PP + p] : 0.0f;
        float w1 = (j1 < H1) ? W2[j1 * PP + p] : 0.0f;
        W2T[i] = cvtbf2(w1, w0);
    }
    for (int i = tid; i < 160; i += 128) b1f[i] = (i < H1) ? b1[i] : 0.0f;
    if (tid < PP) b2f[tid] = b2[tid];
    // W3q[q][j][e] = W3[(4q+e)*H1 + j], j padded to 152
    for (int i = tid; i < 10 * 152 * 4; i += 128) {
        int q = i / 608, rem = i - q * 608;
        int j = rem >> 2, e = rem & 3;
        W3q[i] = (j < H1) ? W3[(4 * q + e) * H1 + j] : 0.0f;
    }
    for (int i = tid; i < 152; i += 128) {
        b3s[i] = (i < H1) ? b3[i] : 0.0f;
        W4s[i] = (i < H1) ? W4[i] : 0.0f;
    }
    const float b4v = __ldg(b4);
    __syncthreads();

    const int warp = tid >> 5;
    const int lane = tid & 31;
    const int g0 = (blockIdx.x * 4 + warp) * 4;   // 4 groups per warp
    const int lq = lane >> 2;                      // fragment row (0..7)
    const int lc = lane & 3;                       // fragment col (0..3)

    char* inbw = (char*)(sm + SM_INB) + warp * 8192;   // 128 rows x 64 B bf16
    char* aw   = inbw;                                 // overlay: 128 x 32 B f32

    // ---- stage this warp's 128 reads as swizzled bf16 rows ----
    #pragma unroll
    for (int i = 0; i < 4; ++i) {
        const int rr = i * 32 + lane;
        const int r = indices[(g0 + i) * 32 + lane];
        const float4* px = (const float4*)(x + (size_t)r * 16);
        float4 v0 = px[0], v1 = px[1], v2 = px[2], v3 = px[3];
        float2 e = ((const float2*)emb)[kmer[r]];
        uint4 c0 = make_uint4(cvtbf2(v0.y, v0.x), cvtbf2(v0.w, v0.z),
                              cvtbf2(v1.y, v1.x), cvtbf2(v1.w, v1.z));
        uint4 c1 = make_uint4(cvtbf2(v2.y, v2.x), cvtbf2(v2.w, v2.z),
                              cvtbf2(v3.y, v3.x), cvtbf2(v3.w, v3.z));
        uint4 c2 = make_uint4(cvtbf2(e.y, e.x), 0u, 0u, 0u);
        uint4 c3 = make_uint4(0u, 0u, 0u, 0u);
        uint4* dst = (uint4*)(inbw + rr * 64);
        int sw = (rr >> 1) & 3;
        dst[0 ^ sw] = c0;
        dst[1 ^ sw] = c1;
        dst[2 ^ sw] = c2;
        dst[3 ^ sw] = c3;
    }
    __syncwarp();

    const float2 b2p = *(const float2*)(b2f + 2 * lc);
    const int swf = (lq >> 1) & 3;                // fragment-load swizzle

    // ---- two passes of 64 reads: GEMM1 (relu) chained into GEMM2 ----
    #pragma unroll 1
    for (int pass = 0; pass < 2; ++pass) {
        u32 Af[4][8];
        #pragma unroll
        for (int m = 0; m < 4; ++m) {
            const char* base = inbw + (pass * 64 + m * 16 + lq) * 64 + lc * 4;
            Af[m][0] = *(const u32*)(base + ((0 ^ swf) << 4));
            Af[m][1] = *(const u32*)(base + 8 * 64 + ((0 ^ swf) << 4));
            Af[m][2] = *(const u32*)(base + ((1 ^ swf) << 4));
            Af[m][3] = *(const u32*)(base + 8 * 64 + ((1 ^ swf) << 4));
            Af[m][4] = *(const u32*)(base + ((2 ^ swf) << 4));
            Af[m][5] = *(const u32*)(base + 8 * 64 + ((2 ^ swf) << 4));
            Af[m][6] = *(const u32*)(base + ((3 ^ swf) << 4));
            Af[m][7] = *(const u32*)(base + 8 * 64 + ((3 ^ swf) << 4));
        }

        float C2[4][4];
        #pragma unroll
        for (int m = 0; m < 4; ++m)
            C2[m][0] = C2[m][1] = C2[m][2] = C2[m][3] = 0.0f;

        u32 a2f[4][4];

        #pragma unroll 1
        for (int t = 0; t < 10; ++t) {
            #pragma unroll
            for (int half = 0; half < 2; ++half) {
                const int n = 2 * t + half;
                const int j = 8 * n + lq;
                const char* wb = (const char*)W1T + j * 64 + lc * 4;
                u32 b00 = *(const u32*)(wb + ((0 ^ swf) << 4));
                u32 b01 = *(const u32*)(wb + ((1 ^ swf) << 4));
                u32 b10 = *(const u32*)(wb + ((2 ^ swf) << 4));
                u32 b11 = *(const u32*)(wb + ((3 ^ swf) << 4));
                float2 b1p = *(const float2*)(b1f + 8 * n + 2 * lc);
                #pragma unroll
                for (int m = 0; m < 4; ++m) {
                    float c0, c1, c2, c3;
                    mma16816(c0, c1, c2, c3,
                             Af[m][0], Af[m][1], Af[m][2], Af[m][3],
                             b00, b01, 0.0f, 0.0f, 0.0f, 0.0f);
                    mma16816(c0, c1, c2, c3,
                             Af[m][4], Af[m][5], Af[m][6], Af[m][7],
                             b10, b11, c0, c1, c2, c3);
                    float h0 = fmaxf(c0 + b1p.x, 0.0f);
                    float h1 = fmaxf(c1 + b1p.y, 0.0f);
                    float h2 = fmaxf(c2 + b1p.x, 0.0f);
                    float h3 = fmaxf(c3 + b1p.y, 0.0f);
                    a2f[m][2 * half]     = cvtbf2(h1, h0);
                    a2f[m][2 * half + 1] = cvtbf2(h3, h2);
                }
            }
            {
                const char* w2b = (const char*)W2T + lq * 320 + (16 * t + 2 * lc) * 2;
                u32 w20 = *(const u32*)(w2b);
                u32 w21 = *(const u32*)(w2b + 16);
                #pragma unroll
                for (int m = 0; m < 4; ++m) {
                    mma16816(C2[m][0], C2[m][1], C2[m][2], C2[m][3],
                             a2f[m][0], a2f[m][1], a2f[m][2], a2f[m][3],
                             w20, w21,
                             C2[m][0], C2[m][1], C2[m][2], C2[m][3]);
                }
            }
        }

        // a = relu(C2 + b2) -> aw[r][p], 1-bit chunk swizzle by (r>>2)&1
        #pragma unroll
        for (int m = 0; m < 4; ++m) {
            int rb = pass * 64 + m * 16 + lq;
            int sa = ((rb >> 2) & 1) << 4;
            float2 lo = make_float2(fmaxf(C2[m][0] + b2p.x, 0.0f),
                                    fmaxf(C2[m][1] + b2p.y, 0.0f));
            float2 hi = make_float2(fmaxf(C2[m][2] + b2p.x, 0.0f),
                                    fmaxf(C2[m][3] + b2p.y, 0.0f));
            *(float2*)(aw + rb * 32 + ((lc * 8) ^ sa))       = lo;
            *(float2*)(aw + (rb + 8) * 32 + ((lc * 8) ^ sa)) = hi;
        }
    }
    __syncwarp();

    // ---- per-group aggregation + group MLP (verified tail) ----
    #pragma unroll 1
    for (int i = 0; i < 4; ++i) {
        int rr = i * 32 + lane;
        int sa = ((rr >> 2) & 1) << 4;
        float4 qa = *(const float4*)(aw + rr * 32 + (0 ^ sa));
        float4 qb = *(const float4*)(aw + rr * 32 + (16 ^ sa));
        float s[PP] = {qa.x, qa.y, qa.z, qa.w, qb.x, qb.y, qb.z, qb.w};
        float o = group_tail(s, W3q, b3s, W4s, b4v, lane);
        if (lane == 0) out[g0 + i] = o;
    }
}

extern "C" void kernel_launch(void* const* d_in, const int* in_sizes, int n_in,
                              void* d_out, int out_size)
{
    const float* x       = (const float*)d_in[0];
    const int*   kmer    = (const int*)  d_in[1];
    const int*   indices = (const int*)  d_in[2];
    const float* emb     = (const float*)d_in[3];
    const float* W1      = (const float*)d_in[4];
    const float* b1      = (const float*)d_in[5];
    const float* W2      = (const float*)d_in[6];
    const float* b2      = (const float*)d_in[7];
    const float* W3      = (const float*)d_in[8];
    const float* b3      = (const float*)d_in[9];
    const float* W4      = (const float*)d_in[10];
    const float* b4      = (const float*)d_in[11];
    float* out = (float*)d_out;

    cudaFuncSetAttribute(minn_fused_mma2_kernel,
                         cudaFuncAttributeMaxDynamicSharedMemorySize, SM_BYTES);

    // 4 warps/block * 4 groups/warp = 16 groups per block
    const int blocks = G_TOTAL / 16;   // 2048
    minn_fused_mma2_kernel<<<blocks, 128, SM_BYTES>>>(
        x, kmer, indices, emb, W1, b1, W2, b2, W3, b3, W4, b4, out);
}

// round 14
// speedup vs baseline: 2.2440x; 1.2365x over previous
#include <cuda_runtime.h>

#define G_TOTAL 32768
#define H1      150
#define PP      8

using u64 = unsigned long long;
using u32 = unsigned int;

// ---- packed f32x2 helpers (verified) ----------------------------------------
__device__ __forceinline__ u64 pk2(float a, float b) {
    u64 r;
    asm("mov.b64 %0,{%1,%2};" : "=l"(r)
        : "r"(__float_as_uint(a)), "r"(__float_as_uint(b)));
    return r;
}
__device__ __forceinline__ float2 upk2(u64 v) {
    unsigned lo, hi;
    asm("mov.b64 {%0,%1},%2;" : "=r"(lo), "=r"(hi) : "l"(v));
    return make_float2(__uint_as_float(lo), __uint_as_float(hi));
}
__device__ __forceinline__ u64 fma2(u64 a, u64 b, u64 c) {
    u64 d;
    asm("fma.rn.f32x2 %0,%1,%2,%3;" : "=l"(d) : "l"(a), "l"(b), "l"(c));
    return d;
}

// ---- bf16 / mma helpers ------------------------------------------------------
__device__ __forceinline__ u32 cvtbf2(float hi, float lo) {
    u32 d;
    asm("cvt.rn.bf16x2.f32 %0,%1,%2;" : "=r"(d) : "f"(hi), "f"(lo));
    return d;
}
__device__ __forceinline__ void mma16816(float& d0, float& d1, float& d2, float& d3,
                                         u32 a0, u32 a1, u32 a2, u32 a3,
                                         u32 b0, u32 b1,
                                         float c0, float c1, float c2, float c3)
{
    asm volatile("mma.sync.aligned.m16n8k16.row.col.f32.bf16.bf16.f32 "
                 "{%0,%1,%2,%3},{%4,%5,%6,%7},{%8,%9},{%10,%11,%12,%13};"
                 : "=f"(d0), "=f"(d1), "=f"(d2), "=f"(d3)
                 : "r"(a0), "r"(a1), "r"(a2), "r"(a3), "r"(b0), "r"(b1),
                   "f"(c0), "f"(c1), "f"(c2), "f"(c3));
}

// ---- shared-memory layout (float offsets) ------------------------------------
// W1T : [160 j][32 k] bf16, 16B-chunk-swizzled rows   2560 floats
// W2T : [8 p][160 j] bf16                              640
// b1f : [160] f32                                      160
// b2f : [8] f32                                        8
// b3s : [152] f32                                      152
// W4s : [152] f32                                      152
// W3q : [10 q][152 j][4] f32 (tail, contiguous in j)   6080
// inb : 4 warps x 2048 floats (128 rows x 64B bf16)    8192
//       overlay per warp slice: [0,4096)B = aw[128][8] f32 activations
//                               [4096,4736)B = agg[4 g][40] f32 stats
#define SM_W1T 0
#define SM_W2T 2560
#define SM_B1F 3200
#define SM_B2F 3360
#define SM_B3  3368
#define SM_W4  3520
#define SM_W3Q 3672
#define SM_INB 9752
#define SM_FLOATS (9752 + 8192)
#define SM_BYTES  (SM_FLOATS * 4)

// ---- group MLP tail: agg (precomputed stats) -> 150 relu -> 1 sigmoid --------
__device__ __noinline__ float group_tail2(const u64* __restrict__ agp,
                                          const float* __restrict__ W3q,
                                          const float* __restrict__ b3s,
                                          const float* __restrict__ W4s,
                                          float b4v, int lane)
{
    u64 ag[20];
    #pragma unroll
    for (int q = 0; q < 20; ++q) ag[q] = agp[q];   // broadcast LDS.64

    float zp = 0.0f;
    #pragma unroll 1
    for (int j = lane; j < H1; j += 32) {
        u64 t2a = 0ull, t2b = 0ull;
        #pragma unroll
        for (int q = 0; q < 10; ++q) {
            ulonglong2 w = *(const ulonglong2*)(W3q + (q * 152 + j) * 4);
            t2a = fma2(ag[2 * q],     w.x, t2a);
            t2b = fma2(ag[2 * q + 1], w.y, t2b);
        }
        float2 sa = upk2(t2a), sb = upk2(t2b);
        float t = (sa.x + sa.y) + (sb.x + sb.y) + b3s[j];
        t = fmaxf(t, 0.0f);
        zp = fmaf(t, W4s[j], zp);
    }
    #pragma unroll
    for (int o = 16; o; o >>= 1) zp += __shfl_xor_sync(0xffffffffu, zp, o);

    return 1.0f / (1.0f + __expf(-(zp + b4v)));
}

__global__ void __launch_bounds__(128, 3)
minn_fused_mma3_kernel(const float* __restrict__ x,
                       const int*   __restrict__ kmer,
                       const int*   __restrict__ indices,
                       const float* __restrict__ emb,
                       const float* __restrict__ W1, const float* __restrict__ b1,
                       const float* __restrict__ W2, const float* __restrict__ b2,
                       const float* __restrict__ W3, const float* __restrict__ b3,
                       const float* __restrict__ W4, const float* __restrict__ b4,
                       float* __restrict__ out)
{
    extern __shared__ float sm[];
    u32*   W1T = (u32*)(sm + SM_W1T);
    u32*   W2T = (u32*)(sm + SM_W2T);
    float* b1f = sm + SM_B1F;
    float* b2f = sm + SM_B2F;
    float* b3s = sm + SM_B3;
    float* W4s = sm + SM_W4;
    float* W3q = sm + SM_W3Q;

    const int tid = threadIdx.x;

    // ---- stage weight tables (block-cooperative) ----
    for (int i = tid; i < 160 * 16; i += 128) {
        int j = i >> 4, kp = i & 15;
        int k0 = 2 * kp, k1 = 2 * kp + 1;
        float w0 = (j < H1 && k0 < 18) ? W1[k0 * H1 + j] : 0.0f;
        float w1 = (j < H1 && k1 < 18) ? W1[k1 * H1 + j] : 0.0f;
        int chunk = kp >> 2, e = kp & 3;
        int sw = (j >> 1) & 3;
        W1T[j * 16 + ((chunk ^ sw) << 2) + e] = cvtbf2(w1, w0);
    }
    for (int i = tid; i < 8 * 80; i += 128) {
        int p = i / 80, jp = i - p * 80;
        int j0 = 2 * jp, j1 = j0 + 1;
        float w0 = (j0 < H1) ? W2[j0 * PP + p] : 0.0f;
        float w1 = (j1 < H1) ? W2[j1 * PP + p] : 0.0f;
        W2T[i] = cvtbf2(w1, w0);
    }
    for (int i = tid; i < 160; i += 128) b1f[i] = (i < H1) ? b1[i] : 0.0f;
    if (tid < PP) b2f[tid] = b2[tid];
    for (int i = tid; i < 10 * 152 * 4; i += 128) {
        int q = i / 608, rem = i - q * 608;
        int j = rem >> 2, e = rem & 3;
        W3q[i] = (j < H1) ? W3[(4 * q + e) * H1 + j] : 0.0f;
    }
    for (int i = tid; i < 152; i += 128) {
        b3s[i] = (i < H1) ? b3[i] : 0.0f;
        W4s[i] = (i < H1) ? W4[i] : 0.0f;
    }
    const float b4v = __ldg(b4);
    __syncthreads();

    const int warp = tid >> 5;
    const int lane = tid & 31;
    const int g0 = (blockIdx.x * 4 + warp) * 4;   // 4 groups per warp
    const int lq = lane >> 2;                      // fragment row (0..7)
    const int lc = lane & 3;                       // fragment col (0..3)

    char* inbw = (char*)(sm + SM_INB) + warp * 8192;   // 128 rows x 64 B bf16
    char* aw   = inbw;                                 // overlay: 128 x 32 B f32
    float* agg = (float*)(inbw + 4096);                // overlay: [4 g][40] f32

    // ---- stage this warp's 128 reads as swizzled bf16 rows ----
    #pragma unroll
    for (int i = 0; i < 4; ++i) {
        const int rr = i * 32 + lane;
        const int r = indices[(g0 + i) * 32 + lane];
        const float4* px = (const float4*)(x + (size_t)r * 16);
        float4 v0 = px[0], v1 = px[1], v2 = px[2], v3 = px[3];
        float2 e = ((const float2*)emb)[kmer[r]];
        uint4 c0 = make_uint4(cvtbf2(v0.y, v0.x), cvtbf2(v0.w, v0.z),
                              cvtbf2(v1.y, v1.x), cvtbf2(v1.w, v1.z));
        uint4 c1 = make_uint4(cvtbf2(v2.y, v2.x), cvtbf2(v2.w, v2.z),
                              cvtbf2(v3.y, v3.x), cvtbf2(v3.w, v3.z));
        uint4 c2 = make_uint4(cvtbf2(e.y, e.x), 0u, 0u, 0u);
        uint4 c3 = make_uint4(0u, 0u, 0u, 0u);
        uint4* dst = (uint4*)(inbw + rr * 64);
        int sw = (rr >> 1) & 3;
        dst[0 ^ sw] = c0;
        dst[1 ^ sw] = c1;
        dst[2 ^ sw] = c2;
        dst[3 ^ sw] = c3;
    }
    __syncwarp();

    const float2 b2p = *(const float2*)(b2f + 2 * lc);
    const int swf = (lq >> 1) & 3;                // fragment-load swizzle

    // ---- two passes of 64 reads: GEMM1 (relu) chained into GEMM2 ----
    #pragma unroll 1
    for (int pass = 0; pass < 2; ++pass) {
        u32 Af[4][8];
        #pragma unroll
        for (int m = 0; m < 4; ++m) {
            const char* base = inbw + (pass * 64 + m * 16 + lq) * 64 + lc * 4;
            Af[m][0] = *(const u32*)(base + ((0 ^ swf) << 4));
            Af[m][1] = *(const u32*)(base + 8 * 64 + ((0 ^ swf) << 4));
            Af[m][2] = *(const u32*)(base + ((1 ^ swf) << 4));
            Af[m][3] = *(const u32*)(base + 8 * 64 + ((1 ^ swf) << 4));
            Af[m][4] = *(const u32*)(base + ((2 ^ swf) << 4));
            Af[m][5] = *(const u32*)(base + 8 * 64 + ((2 ^ swf) << 4));
            Af[m][6] = *(const u32*)(base + ((3 ^ swf) << 4));
            Af[m][7] = *(const u32*)(base + 8 * 64 + ((3 ^ swf) << 4));
        }

        float C2[4][4];
        #pragma unroll
        for (int m = 0; m < 4; ++m)
            C2[m][0] = C2[m][1] = C2[m][2] = C2[m][3] = 0.0f;

        u32 a2f[4][4];

        #pragma unroll 1
        for (int t = 0; t < 10; ++t) {
            #pragma unroll
            for (int half = 0; half < 2; ++half) {
                const int n = 2 * t + half;
                const int j = 8 * n + lq;
                const char* wb = (const char*)W1T + j * 64 + lc * 4;
                u32 b00 = *(const u32*)(wb + ((0 ^ swf) << 4));
                u32 b01 = *(const u32*)(wb + ((1 ^ swf) << 4));
                u32 b10 = *(const u32*)(wb + ((2 ^ swf) << 4));
                u32 b11 = *(const u32*)(wb + ((3 ^ swf) << 4));
                float2 b1p = *(const float2*)(b1f + 8 * n + 2 * lc);
                #pragma unroll
                for (int m = 0; m < 4; ++m) {
                    float c0, c1, c2, c3;
                    mma16816(c0, c1, c2, c3,
                             Af[m][0], Af[m][1], Af[m][2], Af[m][3],
                             b00, b01, 0.0f, 0.0f, 0.0f, 0.0f);
                    mma16816(c0, c1, c2, c3,
                             Af[m][4], Af[m][5], Af[m][6], Af[m][7],
                             b10, b11, c0, c1, c2, c3);
                    float h0 = fmaxf(c0 + b1p.x, 0.0f);
                    float h1 = fmaxf(c1 + b1p.y, 0.0f);
                    float h2 = fmaxf(c2 + b1p.x, 0.0f);
                    float h3 = fmaxf(c3 + b1p.y, 0.0f);
                    a2f[m][2 * half]     = cvtbf2(h1, h0);
                    a2f[m][2 * half + 1] = cvtbf2(h3, h2);
                }
            }
            {
                const char* w2b = (const char*)W2T + lq * 320 + (16 * t + 2 * lc) * 2;
                u32 w20 = *(const u32*)(w2b);
                u32 w21 = *(const u32*)(w2b + 16);
                #pragma unroll
                for (int m = 0; m < 4; ++m) {
                    mma16816(C2[m][0], C2[m][1], C2[m][2], C2[m][3],
                             a2f[m][0], a2f[m][1], a2f[m][2], a2f[m][3],
                             w20, w21,
                             C2[m][0], C2[m][1], C2[m][2], C2[m][3]);
                }
            }
        }

        // a = relu(C2 + b2) -> aw[r][p] (plain layout)
        #pragma unroll
        for (int m = 0; m < 4; ++m) {
            int rb = pass * 64 + m * 16 + lq;
            float2 lo = make_float2(fmaxf(C2[m][0] + b2p.x, 0.0f),
                                    fmaxf(C2[m][1] + b2p.y, 0.0f));
            float2 hi = make_float2(fmaxf(C2[m][2] + b2p.x, 0.0f),
                                    fmaxf(C2[m][3] + b2p.y, 0.0f));
            *(float2*)(aw + rb * 32 + lc * 8)       = lo;
            *(float2*)(aw + (rb + 8) * 32 + lc * 8) = hi;
        }
    }
    __syncwarp();

    // ---- per-(group,feature) stats in registers: thread = (g, p) ----
    {
        const int sg = lane >> 3;      // group within warp (0..3)
        const int sp = lane & 7;       // feature (0..7)
        const char* colp = aw + sg * 32 * 32 + sp * 4;

        float v[32];
        float sum = 0.0f;
        #pragma unroll
        for (int i = 0; i < 32; ++i) {
            v[i] = *(const float*)(colp + i * 32);
            sum += v[i];
        }
        float mean = sum * (1.0f / 32.0f);
        float qacc = 0.0f;
        #pragma unroll
        for (int i = 0; i < 32; ++i) {
            float d = v[i] - mean;
            qacc = fmaf(d, d, qacc);
        }
        float var = qacc * (1.0f / 31.0f);

        // in-register bitonic sort (ascending), fully unrolled (240 CEs)
        #pragma unroll
        for (int k = 2; k <= 32; k <<= 1) {
            #pragma unroll
            for (int j = k >> 1; j > 0; j >>= 1) {
                #pragma unroll
                for (int i = 0; i < 32; ++i) {
                    int l = i ^ j;
                    if (l > i) {
                        bool up = ((i & k) == 0);
                        float lo = fminf(v[i], v[l]);
                        float hi = fmaxf(v[i], v[l]);
                        v[i] = up ? lo : hi;
                        v[l] = up ? hi : lo;
                    }
                }
            }
        }

        // agg[g][stat*8 + p]: mean, var, min, median(lower), max
        float* aggw = agg + sg * 40 + sp;
        aggw[0]  = mean;
        aggw[8]  = var;
        aggw[16] = v[0];
        aggw[24] = v[15];
        aggw[32] = v[31];
    }
    __syncwarp();

    // ---- group MLP tail (verified j-loop), stats from smem ----
    #pragma unroll 1
    for (int i = 0; i < 4; ++i) {
        float o = group_tail2((const u64*)(agg + i * 40),
                              W3q, b3s, W4s, b4v, lane);
        if (lane == 0) out[g0 + i] = o;
    }
}

extern "C" void kernel_launch(void* const* d_in, const int* in_sizes, int n_in,
                              void* d_out, int out_size)
{
    const float* x       = (const float*)d_in[0];
    const int*   kmer    = (const int*)  d_in[1];
    const int*   indices = (const int*)  d_in[2];
    const float* emb     = (const float*)d_in[3];
    const float* W1      = (const float*)d_in[4];
    const float* b1      = (const float*)d_in[5];
    const float* W2      = (const float*)d_in[6];
    const float* b2      = (const float*)d_in[7];
    const float* W3      = (const float*)d_in[8];
    const float* b3      = (const float*)d_in[9];
    const float* W4      = (const float*)d_in[10];
    const float* b4      = (const float*)d_in[11];
    float* out = (float*)d_out;

    cudaFuncSetAttribute(minn_fused_mma3_kernel,
                         cudaFuncAttributeMaxDynamicSharedMemorySize, SM_BYTES);

    // 4 warps/block * 4 groups/warp = 16 groups per block
    const int blocks = G_TOTAL / 16;   // 2048
    minn_fused_mma3_kernel<<<blocks, 128, SM_BYTES>>>(
        x, kmer, indices, emb, W1, b1, W2, b2, W3, b3, W4, b4, out);
}

// round 15
// speedup vs baseline: 2.8141x; 1.2541x over previous
#include <cuda_runtime.h>

#define G_TOTAL 32768
#define H1      150
#define PP      8

using u64 = unsigned long long;
using u32 = unsigned int;

// ---- packed f32x2 helpers (verified) ----------------------------------------
__device__ __forceinline__ u64 pk2(float a, float b) {
    u64 r;
    asm("mov.b64 %0,{%1,%2};" : "=l"(r)
        : "r"(__float_as_uint(a)), "r"(__float_as_uint(b)));
    return r;
}
__device__ __forceinline__ float2 upk2(u64 v) {
    unsigned lo, hi;
    asm("mov.b64 {%0,%1},%2;" : "=r"(lo), "=r"(hi) : "l"(v));
    return make_float2(__uint_as_float(lo), __uint_as_float(hi));
}
__device__ __forceinline__ u64 fma2(u64 a, u64 b, u64 c) {
    u64 d;
    asm("fma.rn.f32x2 %0,%1,%2,%3;" : "=l"(d) : "l"(a), "l"(b), "l"(c));
    return d;
}

// ---- bf16 / mma helpers ------------------------------------------------------
__device__ __forceinline__ u32 cvtbf2(float hi, float lo) {
    u32 d;
    asm("cvt.rn.bf16x2.f32 %0,%1,%2;" : "=r"(d) : "f"(hi), "f"(lo));
    return d;
}
__device__ __forceinline__ void mma16816(float& d0, float& d1, float& d2, float& d3,
                                         u32 a0, u32 a1, u32 a2, u32 a3,
                                         u32 b0, u32 b1,
                                         float c0, float c1, float c2, float c3)
{
    asm volatile("mma.sync.aligned.m16n8k16.row.col.f32.bf16.bf16.f32 "
                 "{%0,%1,%2,%3},{%4,%5,%6,%7},{%8,%9},{%10,%11,%12,%13};"
                 : "=f"(d0), "=f"(d1), "=f"(d2), "=f"(d3)
                 : "r"(a0), "r"(a1), "r"(a2), "r"(a3), "r"(b0), "r"(b1),
                   "f"(c0), "f"(c1), "f"(c2), "f"(c3));
}

// ---- shared-memory layout (float offsets) ------------------------------------
// k padded to 24 only (48B rows; second MMA upper half fed with zero regs)
// W1T : [160 j][24 k] bf16 (12 u32/row, 48B)          1920 floats
// W2T : [8 p][160 j] bf16                              640
// b1f : [160] f32                                      160
// b2f : [8]                                            8
// b3s : [152]                                          152
// W4s : [152]                                          152
// W3q : [10 q][152 j][4] f32                           6080
// inb : 8 warps x 1536 floats (128 rows x 48B bf16)    12288
//       overlay per warp slice (6144 B):
//         [0,4224)B  = aw: 4 groups x (32 rows x 32B + 32B pad) f32
//         [4224,4864)B = agg[4 g][40] f32
#define SM_W1T 0
#define SM_W2T 1920
#define SM_B1F 2560
#define SM_B2F 2720
#define SM_B3  2728
#define SM_W4  2880
#define SM_W3Q 3032
#define SM_INB 9112
#define SM_FLOATS (9112 + 12288)
#define SM_BYTES  (SM_FLOATS * 4)

#define AW_GSTRIDE 1056   // bytes per group slice in aw (32*32 + 32 pad)

// ---- group MLP tail: agg (precomputed stats) -> 150 relu -> 1 sigmoid --------
__device__ __noinline__ float group_tail2(const u64* __restrict__ agp,
                                          const float* __restrict__ W3q,
                                          const float* __restrict__ b3s,
                                          const float* __restrict__ W4s,
                                          float b4v, int lane)
{
    u64 ag[20];
    #pragma unroll
    for (int q = 0; q < 20; ++q) ag[q] = agp[q];   // broadcast LDS.64

    float zp = 0.0f;
    #pragma unroll 1
    for (int j = lane; j < H1; j += 32) {
        u64 t2a = 0ull, t2b = 0ull;
        #pragma unroll
        for (int q = 0; q < 10; ++q) {
            ulonglong2 w = *(const ulonglong2*)(W3q + (q * 152 + j) * 4);
            t2a = fma2(ag[2 * q],     w.x, t2a);
            t2b = fma2(ag[2 * q + 1], w.y, t2b);
        }
        float2 sa = upk2(t2a), sb = upk2(t2b);
        float t = (sa.x + sa.y) + (sb.x + sb.y) + b3s[j];
        t = fmaxf(t, 0.0f);
        zp = fmaf(t, W4s[j], zp);
    }
    #pragma unroll
    for (int o = 16; o; o >>= 1) zp += __shfl_xor_sync(0xffffffffu, zp, o);

    return 1.0f / (1.0f + __expf(-(zp + b4v)));
}

__global__ void __launch_bounds__(256, 2)
minn_fused_mma4_kernel(const float* __restrict__ x,
                       const int*   __restrict__ kmer,
                       const int*   __restrict__ indices,
                       const float* __restrict__ emb,
                       const float* __restrict__ W1, const float* __restrict__ b1,
                       const float* __restrict__ W2, const float* __restrict__ b2,
                       const float* __restrict__ W3, const float* __restrict__ b3,
                       const float* __restrict__ W4, const float* __restrict__ b4,
                       float* __restrict__ out)
{
    extern __shared__ float sm[];
    u32*   W1T = (u32*)(sm + SM_W1T);
    u32*   W2T = (u32*)(sm + SM_W2T);
    float* b1f = sm + SM_B1F;
    float* b2f = sm + SM_B2F;
    float* b3s = sm + SM_B3;
    float* W4s = sm + SM_W4;
    float* W3q = sm + SM_W3Q;

    const int tid = threadIdx.x;

    // ---- stage weight tables (block-cooperative, 256 threads) ----
    // W1T[j]: 12 u32 bf16x2 k-pairs (k 0..23, zero outside 18k/150j)
    for (int i = tid; i < 160 * 12; i += 256) {
        int j = i / 12, kp = i - j * 12;
        int k0 = 2 * kp, k1 = 2 * kp + 1;
        float w0 = (j < H1 && k0 < 18) ? W1[k0 * H1 + j] : 0.0f;
        float w1 = (j < H1 && k1 < 18) ? W1[k1 * H1 + j] : 0.0f;
        W1T[i] = cvtbf2(w1, w0);
    }
    for (int i = tid; i < 8 * 80; i += 256) {
        int p = i / 80, jp = i - p * 80;
        int j0 = 2 * jp, j1 = j0 + 1;
        float w0 = (j0 < H1) ? W2[j0 * PP + p] : 0.0f;
        float w1 = (j1 < H1) ? W2[j1 * PP + p] : 0.0f;
        W2T[i] = cvtbf2(w1, w0);
    }
    for (int i = tid; i < 160; i += 256) b1f[i] = (i < H1) ? b1[i] : 0.0f;
    if (tid < PP) b2f[tid] = b2[tid];
    for (int i = tid; i < 10 * 152 * 4; i += 256) {
        int q = i / 608, rem = i - q * 608;
        int j = rem >> 2, e = rem & 3;
        W3q[i] = (j < H1) ? W3[(4 * q + e) * H1 + j] : 0.0f;
    }
    for (int i = tid; i < 152; i += 256) {
        b3s[i] = (i < H1) ? b3[i] : 0.0f;
        W4s[i] = (i < H1) ? W4[i] : 0.0f;
    }
    const float b4v = __ldg(b4);
    __syncthreads();

    const int warp = tid >> 5;                     // 0..7
    const int lane = tid & 31;
    const int g0 = (blockIdx.x * 8 + warp) * 4;    // 4 groups per warp
    const int lq = lane >> 2;                      // fragment row (0..7)
    const int lc = lane & 3;                       // fragment col (0..3)

    char* inbw = (char*)(sm + SM_INB) + warp * 6144;   // 128 rows x 48 B bf16
    char* aw   = inbw;                                 // overlay (see layout)
    float* agg = (float*)(inbw + 4224);                // overlay: [4 g][40] f32

    // ---- stage this warp's 128 reads as 48B bf16 rows (conflict-free) ----
    #pragma unroll
    for (int i = 0; i < 4; ++i) {
        const int rr = i * 32 + lane;
        const int r = indices[(g0 + i) * 32 + lane];
        const float4* px = (const float4*)(x + (size_t)r * 16);
        float4 v0 = px[0], v1 = px[1], v2 = px[2], v3 = px[3];
        float2 e = ((const float2*)emb)[kmer[r]];
        uint4* dst = (uint4*)(inbw + rr * 48);
        dst[0] = make_uint4(cvtbf2(v0.y, v0.x), cvtbf2(v0.w, v0.z),
                            cvtbf2(v1.y, v1.x), cvtbf2(v1.w, v1.z));
        dst[1] = make_uint4(cvtbf2(v2.y, v2.x), cvtbf2(v2.w, v2.z),
                            cvtbf2(v3.y, v3.x), cvtbf2(v3.w, v3.z));
        dst[2] = make_uint4(cvtbf2(e.y, e.x), 0u, 0u, 0u);
    }
    __syncwarp();

    const float2 b2p = *(const float2*)(b2f + 2 * lc);

    // ---- two passes of 64 reads: GEMM1 (relu) chained into GEMM2 ----
    #pragma unroll 1
    for (int pass = 0; pass < 2; ++pass) {
        u32 Af[4][6];
        #pragma unroll
        for (int m = 0; m < 4; ++m) {
            const char* base = inbw + (pass * 64 + m * 16 + lq) * 48 + lc * 4;
            Af[m][0] = *(const u32*)(base);
            Af[m][1] = *(const u32*)(base + 8 * 48);
            Af[m][2] = *(const u32*)(base + 16);
            Af[m][3] = *(const u32*)(base + 8 * 48 + 16);
            Af[m][4] = *(const u32*)(base + 32);
            Af[m][5] = *(const u32*)(base + 8 * 48 + 32);
        }

        float C2[4][4];
        #pragma unroll
        for (int m = 0; m < 4; ++m)
            C2[m][0] = C2[m][1] = C2[m][2] = C2[m][3] = 0.0f;

        u32 a2f[4][4];

        #pragma unroll 1
        for (int t = 0; t < 10; ++t) {
            #pragma unroll
            for (int half = 0; half < 2; ++half) {
                const int n = 2 * t + half;
                const int j = 8 * n + lq;
                const char* wb = (const char*)W1T + j * 48 + lc * 4;
                u32 b00 = *(const u32*)(wb);
                u32 b01 = *(const u32*)(wb + 16);
                u32 b10 = *(const u32*)(wb + 32);
                float2 b1p = *(const float2*)(b1f + 8 * n + 2 * lc);
                #pragma unroll
                for (int m = 0; m < 4; ++m) {
                    float c0, c1, c2, c3;
                    mma16816(c0, c1, c2, c3,
                             Af[m][0], Af[m][1], Af[m][2], Af[m][3],
                             b00, b01, 0.0f, 0.0f, 0.0f, 0.0f);
                    // upper k-half (k24..31) is structurally zero:
                    mma16816(c0, c1, c2, c3,
                             Af[m][4], Af[m][5], 0u, 0u,
                             b10, 0u, c0, c1, c2, c3);
                    float h0 = fmaxf(c0 + b1p.x, 0.0f);
                    float h1 = fmaxf(c1 + b1p.y, 0.0f);
                    float h2 = fmaxf(c2 + b1p.x, 0.0f);
                    float h3 = fmaxf(c3 + b1p.y, 0.0f);
                    a2f[m][2 * half]     = cvtbf2(h1, h0);
                    a2f[m][2 * half + 1] = cvtbf2(h3, h2);
                }
            }
            {
                const char* w2b = (const char*)W2T + lq * 320 + (16 * t + 2 * lc) * 2;
                u32 w20 = *(const u32*)(w2b);
                u32 w21 = *(const u32*)(w2b + 16);
                #pragma unroll
                for (int m = 0; m < 4; ++m) {
                    mma16816(C2[m][0], C2[m][1], C2[m][2], C2[m][3],
                             a2f[m][0], a2f[m][1], a2f[m][2], a2f[m][3],
                             w20, w21,
                             C2[m][0], C2[m][1], C2[m][2], C2[m][3]);
                }
            }
        }

        // a = relu(C2 + b2) -> aw[group][row][p], padded group stride
        #pragma unroll
        for (int m = 0; m < 4; ++m) {
            int rb = pass * 64 + m * 16 + lq;
            char* rowlo = aw + (rb >> 5) * AW_GSTRIDE + (rb & 31) * 32;
            int rb2 = rb + 8;
            char* rowhi = aw + (rb2 >> 5) * AW_GSTRIDE + (rb2 & 31) * 32;
            float2 lo = make_float2(fmaxf(C2[m][0] + b2p.x, 0.0f),
                                    fmaxf(C2[m][1] + b2p.y, 0.0f));
            float2 hi = make_float2(fmaxf(C2[m][2] + b2p.x, 0.0f),
                                    fmaxf(C2[m][3] + b2p.y, 0.0f));
            *(float2*)(rowlo + lc * 8) = lo;
            *(float2*)(rowhi + lc * 8) = hi;
        }
    }
    __syncwarp();

    // ---- per-(group,feature) stats in registers: thread = (g, p) ----
    // aw group stride 1056 B -> lane banks sg*8+sp all distinct: conflict-free
    {
        const int sg = lane >> 3;      // group within warp (0..3)
        const int sp = lane & 7;       // feature (0..7)
        const char* colp = aw + sg * AW_GSTRIDE + sp * 4;

        float v[32];
        float sum = 0.0f;
        #pragma unroll
        for (int i = 0; i < 32; ++i) {
            v[i] = *(const float*)(colp + i * 32);
            sum += v[i];
        }
        float mean = sum * (1.0f / 32.0f);
        float qacc = 0.0f;
        #pragma unroll
        for (int i = 0; i < 32; ++i) {
            float d = v[i] - mean;
            qacc = fmaf(d, d, qacc);
        }
        float var = qacc * (1.0f / 31.0f);

        // in-register bitonic sort (ascending), fully unrolled
        #pragma unroll
        for (int k = 2; k <= 32; k <<= 1) {
            #pragma unroll
            for (int j = k >> 1; j > 0; j >>= 1) {
                #pragma unroll
                for (int i = 0; i < 32; ++i) {
                    int l = i ^ j;
                    if (l > i) {
                        bool up = ((i & k) == 0);
                        float lo = fminf(v[i], v[l]);
                        float hi = fmaxf(v[i], v[l]);
                        v[i] = up ? lo : hi;
                        v[l] = up ? hi : lo;
                    }
                }
            }
        }

        float* aggw = agg + sg * 40 + sp;
        aggw[0]  = mean;
        aggw[8]  = var;
        aggw[16] = v[0];
        aggw[24] = v[15];
        aggw[32] = v[31];
    }
    __syncwarp();

    // ---- group MLP tail (verified j-loop), stats from smem ----
    #pragma unroll 1
    for (int i = 0; i < 4; ++i) {
        float o = group_tail2((const u64*)(agg + i * 40),
                              W3q, b3s, W4s, b4v, lane);
        if (lane == 0) out[g0 + i] = o;
    }
}

extern "C" void kernel_launch(void* const* d_in, const int* in_sizes, int n_in,
                              void* d_out, int out_size)
{
    const float* x       = (const float*)d_in[0];
    const int*   kmer    = (const int*)  d_in[1];
    const int*   indices = (const int*)  d_in[2];
    const float* emb     = (const float*)d_in[3];
    const float* W1      = (const float*)d_in[4];
    const float* b1      = (const float*)d_in[5];
    const float* W2      = (const float*)d_in[6];
    const float* b2      = (const float*)d_in[7];
    const float* W3      = (const float*)d_in[8];
    const float* b3      = (const float*)d_in[9];
    const float* W4      = (const float*)d_in[10];
    const float* b4      = (const float*)d_in[11];
    float* out = (float*)d_out;

    cudaFuncSetAttribute(minn_fused_mma4_kernel,
                         cudaFuncAttributeMaxDynamicSharedMemorySize, SM_BYTES);

    // 8 warps/block * 4 groups/warp = 32 groups per block
    const int blocks = G_TOTAL / 32;   // 1024
    minn_fused_mma4_kernel<<<blocks, 256, SM_BYTES>>>(
        x, kmer, indices, emb, W1, b1, W2, b2, W3, b3, W4, b4, out);
}

// round 16
// speedup vs baseline: 2.9512x; 1.0488x over previous
#include <cuda_runtime.h>

#define G_TOTAL 32768
#define H1      150
#define PP      8

using u64 = unsigned long long;
using u32 = unsigned int;

// ---- packed f32x2 helpers (verified) ----------------------------------------
__device__ __forceinline__ u64 pk2(float a, float b) {
    u64 r;
    asm("mov.b64 %0,{%1,%2};" : "=l"(r)
        : "r"(__float_as_uint(a)), "r"(__float_as_uint(b)));
    return r;
}
__device__ __forceinline__ float2 upk2(u64 v) {
    unsigned lo, hi;
    asm("mov.b64 {%0,%1},%2;" : "=r"(lo), "=r"(hi) : "l"(v));
    return make_float2(__uint_as_float(lo), __uint_as_float(hi));
}
__device__ __forceinline__ u64 fma2(u64 a, u64 b, u64 c) {
    u64 d;
    asm("fma.rn.f32x2 %0,%1,%2,%3;" : "=l"(d) : "l"(a), "l"(b), "l"(c));
    return d;
}

// ---- bf16 / mma helpers ------------------------------------------------------
__device__ __forceinline__ u32 cvtbf2(float hi, float lo) {
    u32 d;
    asm("cvt.rn.bf16x2.f32 %0,%1,%2;" : "=r"(d) : "f"(hi), "f"(lo));
    return d;
}
__device__ __forceinline__ void mma16816(float& d0, float& d1, float& d2, float& d3,
                                         u32 a0, u32 a1, u32 a2, u32 a3,
                                         u32 b0, u32 b1,
                                         float c0, float c1, float c2, float c3)
{
    asm volatile("mma.sync.aligned.m16n8k16.row.col.f32.bf16.bf16.f32 "
                 "{%0,%1,%2,%3},{%4,%5,%6,%7},{%8,%9},{%10,%11,%12,%13};"
                 : "=f"(d0), "=f"(d1), "=f"(d2), "=f"(d3)
                 : "r"(a0), "r"(a1), "r"(a2), "r"(a3), "r"(b0), "r"(b1),
                   "f"(c0), "f"(c1), "f"(c2), "f"(c3));
}

// ---- shared-memory layout (float offsets) ------------------------------------
// Biases folded into GEMMs: input k=18 carries 1.0 (W1 row 18 = b1);
// hidden j=150 pinned to 1 (W1T[18][150]=1) with W2 row 150 = b2.
// W1T : [160 j][24 k] bf16 (12 u32/row, 48B)          1920 floats
// W2T : [8 p][160 j] bf16                              640
// b3s : [152]                                          152
// W4s : [152]                                          152
// W3q : [10 q][152 j][4] f32                           6080
// inb : 8 warps x 1536 floats (128 rows x 48B bf16)    12288
//       overlay per warp slice (6144 B):
//         [0,4224)B  = aw: 4 groups x (32 rows x 32B + 32B pad) f32
//         [4224,4864)B = agg[4 g][40] f32
#define SM_W1T 0
#define SM_W2T 1920
#define SM_B3  2560
#define SM_W4  2712
#define SM_W3Q 2864
#define SM_INB 8944
#define SM_FLOATS (8944 + 12288)
#define SM_BYTES  (SM_FLOATS * 4)

#define AW_GSTRIDE 1056   // bytes per group slice in aw (32*32 + 32 pad)

// ---- group MLP tail: agg (precomputed stats) -> 150 relu -> 1 sigmoid --------
__device__ __noinline__ float group_tail2(const u64* __restrict__ agp,
                                          const float* __restrict__ W3q,
                                          const float* __restrict__ b3s,
                                          const float* __restrict__ W4s,
                                          float b4v, int lane)
{
    u64 ag[20];
    #pragma unroll
    for (int q = 0; q < 20; ++q) ag[q] = agp[q];   // broadcast LDS.64

    float zp = 0.0f;
    #pragma unroll 1
    for (int j = lane; j < H1; j += 32) {
        u64 t2a = 0ull, t2b = 0ull;
        #pragma unroll
        for (int q = 0; q < 10; ++q) {
            ulonglong2 w = *(const ulonglong2*)(W3q + (q * 152 + j) * 4);
            t2a = fma2(ag[2 * q],     w.x, t2a);
            t2b = fma2(ag[2 * q + 1], w.y, t2b);
        }
        float2 sa = upk2(t2a), sb = upk2(t2b);
        float t = (sa.x + sa.y) + (sb.x + sb.y) + b3s[j];
        t = fmaxf(t, 0.0f);
        zp = fmaf(t, W4s[j], zp);
    }
    #pragma unroll
    for (int o = 16; o; o >>= 1) zp += __shfl_xor_sync(0xffffffffu, zp, o);

    return 1.0f / (1.0f + __expf(-(zp + b4v)));
}

__global__ void __launch_bounds__(256, 2)
minn_fused_mma5_kernel(const float* __restrict__ x,
                       const int*   __restrict__ kmer,
                       const int*   __restrict__ indices,
                       const float* __restrict__ emb,
                       const float* __restrict__ W1, const float* __restrict__ b1,
                       const float* __restrict__ W2, const float* __restrict__ b2,
                       const float* __restrict__ W3, const float* __restrict__ b3,
                       const float* __restrict__ W4, const float* __restrict__ b4,
                       float* __restrict__ out)
{
    extern __shared__ float sm[];
    u32*   W1T = (u32*)(sm + SM_W1T);
    u32*   W2T = (u32*)(sm + SM_W2T);
    float* b3s = sm + SM_B3;
    float* W4s = sm + SM_W4;
    float* W3q = sm + SM_W3Q;

    const int tid = threadIdx.x;

    // ---- stage weight tables (block-cooperative, 256 threads) ----
    // W1T[j]: 12 u32 bf16x2 k-pairs; k=18 row carries b1[j] (and 1.0 at j=150)
    for (int i = tid; i < 160 * 12; i += 256) {
        int j = i / 12, kp = i - j * 12;
        int k0 = 2 * kp, k1 = 2 * kp + 1;
        float w0 = 0.0f, w1 = 0.0f;
        if (k0 < 18)        w0 = (j < H1) ? W1[k0 * H1 + j] : 0.0f;
        else if (k0 == 18)  w0 = (j < H1) ? b1[j] : (j == H1 ? 1.0f : 0.0f);
        if (k1 < 18)        w1 = (j < H1) ? W1[k1 * H1 + j] : 0.0f;
        else if (k1 == 18)  w1 = (j < H1) ? b1[j] : (j == H1 ? 1.0f : 0.0f);
        W1T[i] = cvtbf2(w1, w0);
    }
    // W2T[p][jpair]; j=150 row carries b2[p]
    for (int i = tid; i < 8 * 80; i += 256) {
        int p = i / 80, jp = i - p * 80;
        int j0 = 2 * jp, j1 = j0 + 1;
        float w0 = (j0 < H1) ? W2[j0 * PP + p] : (j0 == H1 ? b2[p] : 0.0f);
        float w1 = (j1 < H1) ? W2[j1 * PP + p] : (j1 == H1 ? b2[p] : 0.0f);
        W2T[i] = cvtbf2(w1, w0);
    }
    for (int i = tid; i < 10 * 152 * 4; i += 256) {
        int q = i / 608, rem = i - q * 608;
        int j = rem >> 2, e = rem & 3;
        W3q[i] = (j < H1) ? W3[(4 * q + e) * H1 + j] : 0.0f;
    }
    for (int i = tid; i < 152; i += 256) {
        b3s[i] = (i < H1) ? b3[i] : 0.0f;
        W4s[i] = (i < H1) ? W4[i] : 0.0f;
    }
    const float b4v = __ldg(b4);
    __syncthreads();

    const int warp = tid >> 5;                     // 0..7
    const int lane = tid & 31;
    const int g0 = (blockIdx.x * 8 + warp) * 4;    // 4 groups per warp
    const int lq = lane >> 2;                      // fragment row (0..7)
    const int lc = lane & 3;                       // fragment col (0..3)

    char* inbw = (char*)(sm + SM_INB) + warp * 6144;   // 128 rows x 48 B bf16
    char* aw   = inbw;                                 // overlay (see layout)
    float* agg = (float*)(inbw + 4224);                // overlay: [4 g][40] f32

    // ---- stage this warp's 128 reads as 48B bf16 rows (conflict-free) ----
    // k=18 slot = 1.0 (bias lane), k=19..23 = 0
    const u32 ONE18 = cvtbf2(0.0f, 1.0f);
    #pragma unroll
    for (int i = 0; i < 4; ++i) {
        const int rr = i * 32 + lane;
        const int r = indices[(g0 + i) * 32 + lane];
        const float4* px = (const float4*)(x + (size_t)r * 16);
        float4 v0 = px[0], v1 = px[1], v2 = px[2], v3 = px[3];
        float2 e = ((const float2*)emb)[kmer[r]];
        uint4* dst = (uint4*)(inbw + rr * 48);
        dst[0] = make_uint4(cvtbf2(v0.y, v0.x), cvtbf2(v0.w, v0.z),
                            cvtbf2(v1.y, v1.x), cvtbf2(v1.w, v1.z));
        dst[1] = make_uint4(cvtbf2(v2.y, v2.x), cvtbf2(v2.w, v2.z),
                            cvtbf2(v3.y, v3.x), cvtbf2(v3.w, v3.z));
        dst[2] = make_uint4(cvtbf2(e.y, e.x), ONE18, 0u, 0u);
    }
    __syncwarp();

    // ---- two passes of 64 reads: GEMM1 (relu) chained into GEMM2 ----
    #pragma unroll 1
    for (int pass = 0; pass < 2; ++pass) {
        u32 Af[4][6];
        #pragma unroll
        for (int m = 0; m < 4; ++m) {
            const char* base = inbw + (pass * 64 + m * 16 + lq) * 48 + lc * 4;
            Af[m][0] = *(const u32*)(base);
            Af[m][1] = *(const u32*)(base + 8 * 48);
            Af[m][2] = *(const u32*)(base + 16);
            Af[m][3] = *(const u32*)(base + 8 * 48 + 16);
            Af[m][4] = *(const u32*)(base + 32);
            Af[m][5] = *(const u32*)(base + 8 * 48 + 32);
        }

        float C2[4][4];
        #pragma unroll
        for (int m = 0; m < 4; ++m)
            C2[m][0] = C2[m][1] = C2[m][2] = C2[m][3] = 0.0f;

        u32 a2f[4][4];

        #pragma unroll 2
        for (int t = 0; t < 10; ++t) {
            #pragma unroll
            for (int half = 0; half < 2; ++half) {
                const int n = 2 * t + half;
                const int j = 8 * n + lq;
                const char* wb = (const char*)W1T + j * 48 + lc * 4;
                u32 b00 = *(const u32*)(wb);
                u32 b01 = *(const u32*)(wb + 16);
                u32 b10 = *(const u32*)(wb + 32);
                #pragma unroll
                for (int m = 0; m < 4; ++m) {
                    float c0, c1, c2, c3;
                    mma16816(c0, c1, c2, c3,
                             Af[m][0], Af[m][1], Af[m][2], Af[m][3],
                             b00, b01, 0.0f, 0.0f, 0.0f, 0.0f);
                    // upper k-half (k24..31) is structurally zero:
                    mma16816(c0, c1, c2, c3,
                             Af[m][4], Af[m][5], 0u, 0u,
                             b10, 0u, c0, c1, c2, c3);
                    // bias already folded via k=18; straight relu
                    float h0 = fmaxf(c0, 0.0f);
                    float h1 = fmaxf(c1, 0.0f);
                    float h2 = fmaxf(c2, 0.0f);
                    float h3 = fmaxf(c3, 0.0f);
                    a2f[m][2 * half]     = cvtbf2(h1, h0);
                    a2f[m][2 * half + 1] = cvtbf2(h3, h2);
                }
            }
            {
                const char* w2b = (const char*)W2T + lq * 320 + (16 * t + 2 * lc) * 2;
                u32 w20 = *(const u32*)(w2b);
                u32 w21 = *(const u32*)(w2b + 16);
                #pragma unroll
                for (int m = 0; m < 4; ++m) {
                    mma16816(C2[m][0], C2[m][1], C2[m][2], C2[m][3],
                             a2f[m][0], a2f[m][1], a2f[m][2], a2f[m][3],
                             w20, w21,
                             C2[m][0], C2[m][1], C2[m][2], C2[m][3]);
                }
            }
        }

        // a = relu(C2) -> aw[group][row][p]  (b2 folded via j=150)
        #pragma unroll
        for (int m = 0; m < 4; ++m) {
            int rb = pass * 64 + m * 16 + lq;
            char* rowlo = aw + (rb >> 5) * AW_GSTRIDE + (rb & 31) * 32;
            int rb2 = rb + 8;
            char* rowhi = aw + (rb2 >> 5) * AW_GSTRIDE + (rb2 & 31) * 32;
            float2 lo = make_float2(fmaxf(C2[m][0], 0.0f),
                                    fmaxf(C2[m][1], 0.0f));
            float2 hi = make_float2(fmaxf(C2[m][2], 0.0f),
                                    fmaxf(C2[m][3], 0.0f));
            *(float2*)(rowlo + lc * 8) = lo;
            *(float2*)(rowhi + lc * 8) = hi;
        }
    }
    __syncwarp();

    // ---- per-(group,feature) stats in registers: thread = (g, p) ----
    {
        const int sg = lane >> 3;      // group within warp (0..3)
        const int sp = lane & 7;       // feature (0..7)
        const char* colp = aw + sg * AW_GSTRIDE + sp * 4;

        float v[32];
        float sum = 0.0f;
        #pragma unroll
        for (int i = 0; i < 32; ++i) {
            v[i] = *(const float*)(colp + i * 32);
            sum += v[i];
        }
        float mean = sum * (1.0f / 32.0f);
        float qacc = 0.0f;
        #pragma unroll
        for (int i = 0; i < 32; ++i) {
            float d = v[i] - mean;
            qacc = fmaf(d, d, qacc);
        }
        float var = qacc * (1.0f / 31.0f);

        // in-register bitonic sort (ascending), fully unrolled
        #pragma unroll
        for (int k = 2; k <= 32; k <<= 1) {
            #pragma unroll
            for (int j = k >> 1; j > 0; j >>= 1) {
                #pragma unroll
                for (int i = 0; i < 32; ++i) {
                    int l = i ^ j;
                    if (l > i) {
                        bool up = ((i & k) == 0);
                        float lo = fminf(v[i], v[l]);
                        float hi = fmaxf(v[i], v[l]);
                        v[i] = up ? lo : hi;
                        v[l] = up ? hi : lo;
                    }
                }
            }
        }

        float* aggw = agg + sg * 40 + sp;
        aggw[0]  = mean;
        aggw[8]  = var;
        aggw[16] = v[0];
        aggw[24] = v[15];
        aggw[32] = v[31];
    }
    __syncwarp();

    // ---- group MLP tail (verified j-loop), stats from smem ----
    #pragma unroll 1
    for (int i = 0; i < 4; ++i) {
        float o = group_tail2((const u64*)(agg + i * 40),
                              W3q, b3s, W4s, b4v, lane);
        if (lane == 0) out[g0 + i] = o;
    }
}

extern "C" void kernel_launch(void* const* d_in, const int* in_sizes, int n_in,
                              void* d_out, int out_size)
{
    const float* x       = (const float*)d_in[0];
    const int*   kmer    = (const int*)  d_in[1];
    const int*   indices = (const int*)  d_in[2];
    const float* emb     = (const float*)d_in[3];
    const float* W1      = (const float*)d_in[4];
    const float* b1      = (const float*)d_in[5];
    const float* W2      = (const float*)d_in[6];
    const float* b2      = (const float*)d_in[7];
    const float* W3      = (const float*)d_in[8];
    const float* b3      = (const float*)d_in[9];
    const float* W4      = (const float*)d_in[10];
    const float* b4      = (const float*)d_in[11];
    float* out = (float*)d_out;

    cudaFuncSetAttribute(minn_fused_mma5_kernel,
                         cudaFuncAttributeMaxDynamicSharedMemorySize, SM_BYTES);

    // 8 warps/block * 4 groups/warp = 32 groups per block
    const int blocks = G_TOTAL / 32;   // 1024
    minn_fused_mma5_kernel<<<blocks, 256, SM_BYTES>>>(
        x, kmer, indices, emb, W1, b1, W2, b2, W3, b3, W4, b4, out);
}